// round 2
// baseline (speedup 1.0000x reference)
#include <cuda_runtime.h>
#include <cuda_fp16.h>
#include <cuda_fp8.h>
#include <math.h>

#define T_ 512
#define D_ 2048
#define I_ 768
#define E_ 16
#define K_ 8

#define BM 64
#define BN 64
#define BK 32
#define PAD 4

// ---------------- scratch (static device memory; no allocations) ----------------
__device__ float g_xq[T_ * D_];            // fp8 quant-dequantized activations (4 MB)
__device__ float g_a[E_ * T_ * I_];        // per-(expert,slot) activation a = silu(g)*u (25 MB)
__device__ int   g_tok[E_ * T_];           // compacted token list per expert
__device__ int   g_cnt[E_];                // tokens per expert
__device__ float g_comb[T_ * E_];          // summed topk weight per (token, expert)
__device__ int   g_flag[T_ * E_];          // routed flag

__constant__ float c_fp4[16] = {0.0f, 0.5f, 1.0f, 1.5f, 2.0f, 3.0f, 4.0f, 6.0f,
                                -0.0f, -0.5f, -1.0f, -1.5f, -2.0f, -3.0f, -4.0f, -6.0f};

// ---------------- kernel 0: zero output + routing state ----------------
__global__ void zero_kernel(float* __restrict__ out) {
    int i = blockIdx.x * blockDim.x + threadIdx.x;
    if (i < T_ * D_) out[i] = 0.0f;
    if (i < T_ * E_) { g_comb[i] = 0.0f; g_flag[i] = 0; }
    if (i < E_) g_cnt[i] = 0;
}

// ---------------- kernel 1: fp8 (e4m3) group quant-dequant of x ----------------
// One warp per group of 32 contiguous elements (groups are contiguous row-major).
__global__ void quant_kernel(const float* __restrict__ x) {
    int g = blockIdx.x * (blockDim.x >> 5) + (threadIdx.x >> 5);
    int lane = threadIdx.x & 31;
    if (g >= (T_ * D_) / 32) return;
    float v = x[g * 32 + lane];
    float av = fabsf(v);
    #pragma unroll
    for (int o = 16; o; o >>= 1) av = fmaxf(av, __shfl_xor_sync(0xffffffffu, av, o));
    av = fmaxf(av, 1e-4f);
    float scale = av / 448.0f;
    unsigned bits = __float_as_uint(scale);
    unsigned exp = ((bits >> 23) & 255u) + ((bits & 0x7fffffu) ? 1u : 0u);
    exp = min(max(exp, 1u), 254u);
    float rscale = __uint_as_float(exp << 23);
    float inv = 1.0f / rscale;  // exact (power of two)
    __nv_fp8_storage_t q = __nv_cvt_float_to_fp8(v * inv, __NV_SATFINITE, __NV_E4M3);
    float qf = __half2float(__half(__nv_cvt_fp8_to_halfraw(q, __NV_E4M3)));
    g_xq[g * 32 + lane] = qf * rscale;
}

// ---------------- kernel 2: routing build ----------------
__global__ void route_build(const float* __restrict__ tw, const int* __restrict__ tid) {
    int i = blockIdx.x * blockDim.x + threadIdx.x;
    if (i >= T_ * K_) return;
    int t = i / K_;
    int e = tid[i];
    atomicAdd(&g_comb[t * E_ + e], tw[i]);
    g_flag[t * E_ + e] = 1;
}

// ---------------- kernel 3: deterministic compaction (token order preserved) ----------------
__global__ void route_compact() {
    int e = threadIdx.x;
    if (e >= E_) return;
    int c = 0;
    for (int t = 0; t < T_; t++)
        if (g_flag[t * E_ + e]) g_tok[e * T_ + c++] = t;
    g_cnt[e] = c;
}

// ---------------- kernel 4: GEMM1 + SiLU (h = x @ w13^T; a = silu(g)*u) ----------------
// blockIdx.x = i-tile (12), blockIdx.y = token-tile (8), blockIdx.z = expert (16)
__global__ void __launch_bounds__(256, 2)
gemm1_kernel(const int* __restrict__ w13, const int* __restrict__ w13s) {
    const int e = blockIdx.z;
    const int cnt = g_cnt[e];
    const int m0 = blockIdx.y * BM;
    if (m0 >= cnt) return;
    const int n0 = blockIdx.x * BN;

    __shared__ float As[BK][BM + PAD];
    __shared__ float Bgs[BK][BN + PAD];
    __shared__ float Bus[BK][BN + PAD];
    __shared__ float tab[16];
    __shared__ int toks[BM];

    const int tid = threadIdx.x;
    if (tid < 16) tab[tid] = c_fp4[tid];
    if (tid < BM) {
        int m = m0 + tid;
        toks[tid] = g_tok[e * T_ + (m < cnt ? m : 0)];
    }
    __syncthreads();

    const int* we = w13 + (size_t)e * (2 * I_) * (D_ / 2);
    const int* se = w13s + (size_t)e * (2 * I_) * (D_ / 32);

    const int bn = tid >> 2;            // B: row (i) within tile, 0..63
    const int bw = (tid & 3) * 4;       // B: word offset within row slice, {0,4,8,12}
    const int tm = (tid >> 4) << 2;     // compute: token offset
    const int tn = (tid & 15) << 2;     // compute: i offset

    float accg[4][4] = {};
    float accu[4][4] = {};

    for (int k0 = 0; k0 < D_; k0 += BK) {
        // A tile: gather token rows, transposed store As[k][m]
        #pragma unroll
        for (int r = 0; r < 2; r++) {
            int idx = tid + r * 256;
            int row = idx >> 3, c4 = idx & 7;
            float4 v = *reinterpret_cast<const float4*>(
                &g_xq[(size_t)toks[row] * D_ + k0 + c4 * 4]);
            As[c4 * 4 + 0][row] = v.x;
            As[c4 * 4 + 1][row] = v.y;
            As[c4 * 4 + 2][row] = v.z;
            As[c4 * 4 + 3][row] = v.w;
        }
        // B tiles: gate row (n0+bn) and up row (I_+n0+bn), fp4 dequant * ue8m0 scale
        {
            int fg = n0 + bn;
            int fu = I_ + n0 + bn;
            float sg = __uint_as_float(((unsigned)se[fg * (D_ / 32) + (k0 >> 5)]) << 23);
            float su = __uint_as_float(((unsigned)se[fu * (D_ / 32) + (k0 >> 5)]) << 23);
            int4 wg = *reinterpret_cast<const int4*>(&we[(size_t)fg * (D_ / 2) + (k0 >> 1) + bw]);
            int4 wu = *reinterpret_cast<const int4*>(&we[(size_t)fu * (D_ / 2) + (k0 >> 1) + bw]);
            int kl = bw * 2;
            int w;
            w = wg.x; Bgs[kl + 0][bn] = tab[w & 15] * sg; Bgs[kl + 1][bn] = tab[(w >> 4) & 15] * sg;
            w = wg.y; Bgs[kl + 2][bn] = tab[w & 15] * sg; Bgs[kl + 3][bn] = tab[(w >> 4) & 15] * sg;
            w = wg.z; Bgs[kl + 4][bn] = tab[w & 15] * sg; Bgs[kl + 5][bn] = tab[(w >> 4) & 15] * sg;
            w = wg.w; Bgs[kl + 6][bn] = tab[w & 15] * sg; Bgs[kl + 7][bn] = tab[(w >> 4) & 15] * sg;
            w = wu.x; Bus[kl + 0][bn] = tab[w & 15] * su; Bus[kl + 1][bn] = tab[(w >> 4) & 15] * su;
            w = wu.y; Bus[kl + 2][bn] = tab[w & 15] * su; Bus[kl + 3][bn] = tab[(w >> 4) & 15] * su;
            w = wu.z; Bus[kl + 4][bn] = tab[w & 15] * su; Bus[kl + 5][bn] = tab[(w >> 4) & 15] * su;
            w = wu.w; Bus[kl + 6][bn] = tab[w & 15] * su; Bus[kl + 7][bn] = tab[(w >> 4) & 15] * su;
        }
        __syncthreads();

        #pragma unroll
        for (int kk = 0; kk < BK; kk++) {
            float4 av = *reinterpret_cast<const float4*>(&As[kk][tm]);
            float4 bg = *reinterpret_cast<const float4*>(&Bgs[kk][tn]);
            float4 bu = *reinterpret_cast<const float4*>(&Bus[kk][tn]);
            float am[4] = {av.x, av.y, av.z, av.w};
            float gn[4] = {bg.x, bg.y, bg.z, bg.w};
            float un[4] = {bu.x, bu.y, bu.z, bu.w};
            #pragma unroll
            for (int mi = 0; mi < 4; mi++)
                #pragma unroll
                for (int ni = 0; ni < 4; ni++) {
                    accg[mi][ni] += am[mi] * gn[ni];
                    accu[mi][ni] += am[mi] * un[ni];
                }
        }
        __syncthreads();
    }

    // epilogue: a = silu(g) * u, stored by (expert, slot)
    #pragma unroll
    for (int mi = 0; mi < 4; mi++) {
        int m = m0 + tm + mi;
        if (m >= cnt) continue;
        float* arow = &g_a[((size_t)e * T_ + m) * I_ + n0 + tn];
        #pragma unroll
        for (int ni = 0; ni < 4; ni++) {
            float gv = accg[mi][ni];
            float s = 1.0f / (1.0f + expf(-gv));
            arow[ni] = gv * s * accu[mi][ni];
        }
    }
}

// ---------------- kernel 5: GEMM2 + weighted scatter (out += comb * (a @ w2^T)) ----------------
// blockIdx.x = d-tile (32), blockIdx.y = token-tile (8), blockIdx.z = expert (16)
__global__ void __launch_bounds__(256, 2)
gemm2_kernel(const int* __restrict__ w2, const int* __restrict__ w2s, float* __restrict__ out) {
    const int e = blockIdx.z;
    const int cnt = g_cnt[e];
    const int m0 = blockIdx.y * BM;
    if (m0 >= cnt) return;
    const int n0 = blockIdx.x * BN;

    __shared__ float As[BK][BM + PAD];
    __shared__ float Bs[BK][BN + PAD];
    __shared__ float tab[16];
    __shared__ int toks[BM];

    const int tid = threadIdx.x;
    if (tid < 16) tab[tid] = c_fp4[tid];
    if (tid < BM) {
        int m = m0 + tid;
        toks[tid] = g_tok[e * T_ + (m < cnt ? m : 0)];
    }
    __syncthreads();

    const int* we = w2 + (size_t)e * D_ * (I_ / 2);
    const int* se = w2s + (size_t)e * D_ * (I_ / 32);

    const int bn = tid >> 2;
    const int bw = (tid & 3) * 4;
    const int tm = (tid >> 4) << 2;
    const int tn = (tid & 15) << 2;

    float acc[4][4] = {};

    for (int k0 = 0; k0 < I_; k0 += BK) {
        #pragma unroll
        for (int r = 0; r < 2; r++) {
            int idx = tid + r * 256;
            int row = idx >> 3, c4 = idx & 7;
            float4 v = *reinterpret_cast<const float4*>(
                &g_a[((size_t)e * T_ + m0 + row) * I_ + k0 + c4 * 4]);
            As[c4 * 4 + 0][row] = v.x;
            As[c4 * 4 + 1][row] = v.y;
            As[c4 * 4 + 2][row] = v.z;
            As[c4 * 4 + 3][row] = v.w;
        }
        {
            int d = n0 + bn;
            float sc = __uint_as_float(((unsigned)se[d * (I_ / 32) + (k0 >> 5)]) << 23);
            int4 wv = *reinterpret_cast<const int4*>(&we[(size_t)d * (I_ / 2) + (k0 >> 1) + bw]);
            int kl = bw * 2;
            int w;
            w = wv.x; Bs[kl + 0][bn] = tab[w & 15] * sc; Bs[kl + 1][bn] = tab[(w >> 4) & 15] * sc;
            w = wv.y; Bs[kl + 2][bn] = tab[w & 15] * sc; Bs[kl + 3][bn] = tab[(w >> 4) & 15] * sc;
            w = wv.z; Bs[kl + 4][bn] = tab[w & 15] * sc; Bs[kl + 5][bn] = tab[(w >> 4) & 15] * sc;
            w = wv.w; Bs[kl + 6][bn] = tab[w & 15] * sc; Bs[kl + 7][bn] = tab[(w >> 4) & 15] * sc;
        }
        __syncthreads();

        #pragma unroll
        for (int kk = 0; kk < BK; kk++) {
            float4 av = *reinterpret_cast<const float4*>(&As[kk][tm]);
            float4 bv = *reinterpret_cast<const float4*>(&Bs[kk][tn]);
            float am[4] = {av.x, av.y, av.z, av.w};
            float bn4[4] = {bv.x, bv.y, bv.z, bv.w};
            #pragma unroll
            for (int mi = 0; mi < 4; mi++)
                #pragma unroll
                for (int ni = 0; ni < 4; ni++)
                    acc[mi][ni] += am[mi] * bn4[ni];
        }
        __syncthreads();
    }

    #pragma unroll
    for (int mi = 0; mi < 4; mi++) {
        int m = m0 + tm + mi;
        if (m >= cnt) continue;
        int t = toks[tm + mi];
        float c = g_comb[t * E_ + e];
        #pragma unroll
        for (int ni = 0; ni < 4; ni++)
            atomicAdd(&out[(size_t)t * D_ + n0 + tn + ni], c * acc[mi][ni]);
    }
}

// ---------------- launch ----------------
extern "C" void kernel_launch(void* const* d_in, const int* in_sizes, int n_in,
                              void* d_out, int out_size) {
    const float* hs   = (const float*)d_in[0];
    const float* tw   = (const float*)d_in[1];
    const int*   tids = (const int*)d_in[2];
    const int*   w13  = (const int*)d_in[3];
    const int*   w13s = (const int*)d_in[4];
    const int*   w2   = (const int*)d_in[5];
    const int*   w2s  = (const int*)d_in[6];
    float* out = (float*)d_out;

    zero_kernel<<<(T_ * D_ + 255) / 256, 256>>>(out);
    quant_kernel<<<(T_ * D_ / 32 + 7) / 8, 256>>>(hs);
    route_build<<<(T_ * K_ + 255) / 256, 256>>>(tw, tids);
    route_compact<<<1, 32>>>();

    dim3 g1(I_ / BN, T_ / BM, E_);   // 12 x 8 x 16
    gemm1_kernel<<<g1, 256>>>(w13, w13s);

    dim3 g2(D_ / BN, T_ / BM, E_);   // 32 x 8 x 16
    gemm2_kernel<<<g2, 256>>>(w2, w2s, out);
}

// round 3
// speedup vs baseline: 1.0826x; 1.0826x over previous
#include <cuda_runtime.h>
#include <cuda_fp16.h>
#include <cuda_fp8.h>
#include <math.h>

#define T_ 512
#define D_ 2048
#define I_ 768
#define E_ 16
#define K_ 8

#define BM 64
#define BN 64
#define BK 32
#define PAD 4

// packed f32x2 helpers (Blackwell 128-bit fp32 datapath: 2 MACs / FFMA2)
#define FMA2(d, a, b) \
    asm("fma.rn.f32x2 %0, %1, %2, %0;" : "+l"(d) : "l"(a), "l"(b))
#define PACK_DUP(d, f) \
    asm("mov.b64 %0, {%1, %1};" : "=l"(d) : "r"(__float_as_uint(f)))
#define UNPACK2(lo, hi, v) \
    asm("mov.b64 {%0, %1}, %2;" : "=r"(lo), "=r"(hi) : "l"(v))

// ---------------- scratch (static device memory; no allocations) ----------------
__device__ float g_xq[T_ * D_];            // fp8 quant-dequantized activations
__device__ float g_a[E_ * T_ * I_];        // per-(expert,slot) activation a = silu(g)*u
__device__ int   g_tok[E_ * T_];           // compacted token list per expert
__device__ int   g_cnt[E_];                // tokens per expert
__device__ float g_comb[T_ * E_];          // summed topk weight per (token, expert)
__device__ int   g_flag[T_ * E_];          // routed flag

__constant__ float c_fp4[16] = {0.0f, 0.5f, 1.0f, 1.5f, 2.0f, 3.0f, 4.0f, 6.0f,
                                -0.0f, -0.5f, -1.0f, -1.5f, -2.0f, -3.0f, -4.0f, -6.0f};

// ---------------- kernel 0: zero output + routing state ----------------
__global__ void zero_kernel(float* __restrict__ out) {
    int i = blockIdx.x * blockDim.x + threadIdx.x;
    if (i < T_ * D_) out[i] = 0.0f;
    if (i < T_ * E_) { g_comb[i] = 0.0f; g_flag[i] = 0; }
    if (i < E_) g_cnt[i] = 0;
}

// ---------------- kernel 1: fp8 (e4m3) group quant-dequant of x ----------------
__global__ void quant_kernel(const float* __restrict__ x) {
    int g = blockIdx.x * (blockDim.x >> 5) + (threadIdx.x >> 5);
    int lane = threadIdx.x & 31;
    if (g >= (T_ * D_) / 32) return;
    float v = x[g * 32 + lane];
    float av = fabsf(v);
    #pragma unroll
    for (int o = 16; o; o >>= 1) av = fmaxf(av, __shfl_xor_sync(0xffffffffu, av, o));
    av = fmaxf(av, 1e-4f);
    float scale = av / 448.0f;
    unsigned bits = __float_as_uint(scale);
    unsigned exp = ((bits >> 23) & 255u) + ((bits & 0x7fffffu) ? 1u : 0u);
    exp = min(max(exp, 1u), 254u);
    float rscale = __uint_as_float(exp << 23);
    float inv = 1.0f / rscale;  // exact (power of two)
    __nv_fp8_storage_t q = __nv_cvt_float_to_fp8(v * inv, __NV_SATFINITE, __NV_E4M3);
    float qf = __half2float(__half(__nv_cvt_fp8_to_halfraw(q, __NV_E4M3)));
    g_xq[g * 32 + lane] = qf * rscale;
}

// ---------------- kernel 2: routing build ----------------
__global__ void route_build(const float* __restrict__ tw, const int* __restrict__ tid) {
    int i = blockIdx.x * blockDim.x + threadIdx.x;
    if (i >= T_ * K_) return;
    int t = i / K_;
    int e = tid[i];
    atomicAdd(&g_comb[t * E_ + e], tw[i]);
    g_flag[t * E_ + e] = 1;
}

// ---------------- kernel 3: parallel compaction (one block per expert, scan) ----------------
__global__ void route_compact_par() {
    __shared__ int s[T_];
    const int e = blockIdx.x;
    const int t = threadIdx.x;
    int f = g_flag[t * E_ + e];
    s[t] = f;
    __syncthreads();
    #pragma unroll
    for (int off = 1; off < T_; off <<= 1) {
        int v = (t >= off) ? s[t - off] : 0;
        __syncthreads();
        s[t] += v;
        __syncthreads();
    }
    if (f) g_tok[e * T_ + s[t] - 1] = t;
    if (t == T_ - 1) g_cnt[e] = s[t];
}

// ---------------- kernel 4: GEMM1 + SiLU (h = x @ w13^T; a = silu(g)*u) ----------------
__global__ void __launch_bounds__(256, 2)
gemm1_kernel(const int* __restrict__ w13, const int* __restrict__ w13s) {
    const int e = blockIdx.z;
    const int cnt = g_cnt[e];
    const int m0 = blockIdx.y * BM;
    if (m0 >= cnt) return;
    const int n0 = blockIdx.x * BN;

    __shared__ float As[BK][BM + PAD];
    __shared__ float Bgs[BK][BN + PAD];
    __shared__ float Bus[BK][BN + PAD];
    __shared__ float tab[16];
    __shared__ int toks[BM];

    const int tid = threadIdx.x;
    if (tid < 16) tab[tid] = c_fp4[tid];
    if (tid < BM) {
        int m = m0 + tid;
        toks[tid] = g_tok[e * T_ + (m < cnt ? m : 0)];
    }
    __syncthreads();

    const int* we = w13 + (size_t)e * (2 * I_) * (D_ / 2);
    const int* se = w13s + (size_t)e * (2 * I_) * (D_ / 32);

    const int bn = tid >> 2;
    const int bw = (tid & 3) * 4;
    const int tm = (tid >> 4) << 2;
    const int tn = (tid & 15) << 2;

    unsigned long long accg2[4][2] = {};
    unsigned long long accu2[4][2] = {};

    for (int k0 = 0; k0 < D_; k0 += BK) {
        #pragma unroll
        for (int r = 0; r < 2; r++) {
            int idx = tid + r * 256;
            int row = idx >> 3, c4 = idx & 7;
            float4 v = *reinterpret_cast<const float4*>(
                &g_xq[(size_t)toks[row] * D_ + k0 + c4 * 4]);
            As[c4 * 4 + 0][row] = v.x;
            As[c4 * 4 + 1][row] = v.y;
            As[c4 * 4 + 2][row] = v.z;
            As[c4 * 4 + 3][row] = v.w;
        }
        {
            int fg = n0 + bn;
            int fu = I_ + n0 + bn;
            float sg = __uint_as_float(((unsigned)se[fg * (D_ / 32) + (k0 >> 5)]) << 23);
            float su = __uint_as_float(((unsigned)se[fu * (D_ / 32) + (k0 >> 5)]) << 23);
            int4 wg = *reinterpret_cast<const int4*>(&we[(size_t)fg * (D_ / 2) + (k0 >> 1) + bw]);
            int4 wu = *reinterpret_cast<const int4*>(&we[(size_t)fu * (D_ / 2) + (k0 >> 1) + bw]);
            int kl = bw * 2;
            int w;
            w = wg.x; Bgs[kl + 0][bn] = tab[w & 15] * sg; Bgs[kl + 1][bn] = tab[(w >> 4) & 15] * sg;
            w = wg.y; Bgs[kl + 2][bn] = tab[w & 15] * sg; Bgs[kl + 3][bn] = tab[(w >> 4) & 15] * sg;
            w = wg.z; Bgs[kl + 4][bn] = tab[w & 15] * sg; Bgs[kl + 5][bn] = tab[(w >> 4) & 15] * sg;
            w = wg.w; Bgs[kl + 6][bn] = tab[w & 15] * sg; Bgs[kl + 7][bn] = tab[(w >> 4) & 15] * sg;
            w = wu.x; Bus[kl + 0][bn] = tab[w & 15] * su; Bus[kl + 1][bn] = tab[(w >> 4) & 15] * su;
            w = wu.y; Bus[kl + 2][bn] = tab[w & 15] * su; Bus[kl + 3][bn] = tab[(w >> 4) & 15] * su;
            w = wu.z; Bus[kl + 4][bn] = tab[w & 15] * su; Bus[kl + 5][bn] = tab[(w >> 4) & 15] * su;
            w = wu.w; Bus[kl + 6][bn] = tab[w & 15] * su; Bus[kl + 7][bn] = tab[(w >> 4) & 15] * su;
        }
        __syncthreads();

        #pragma unroll
        for (int kk = 0; kk < BK; kk++) {
            float4 av = *reinterpret_cast<const float4*>(&As[kk][tm]);
            ulonglong2 bg = *reinterpret_cast<const ulonglong2*>(&Bgs[kk][tn]);
            ulonglong2 bu = *reinterpret_cast<const ulonglong2*>(&Bus[kk][tn]);
            unsigned long long a2[4];
            PACK_DUP(a2[0], av.x);
            PACK_DUP(a2[1], av.y);
            PACK_DUP(a2[2], av.z);
            PACK_DUP(a2[3], av.w);
            #pragma unroll
            for (int mi = 0; mi < 4; mi++) {
                FMA2(accg2[mi][0], a2[mi], bg.x);
                FMA2(accg2[mi][1], a2[mi], bg.y);
                FMA2(accu2[mi][0], a2[mi], bu.x);
                FMA2(accu2[mi][1], a2[mi], bu.y);
            }
        }
        __syncthreads();
    }

    #pragma unroll
    for (int mi = 0; mi < 4; mi++) {
        int m = m0 + tm + mi;
        if (m >= cnt) continue;
        float* arow = &g_a[((size_t)e * T_ + m) * I_ + n0 + tn];
        #pragma unroll
        for (int p = 0; p < 2; p++) {
            unsigned g0, g1, u0, u1;
            UNPACK2(g0, g1, accg2[mi][p]);
            UNPACK2(u0, u1, accu2[mi][p]);
            float gv0 = __uint_as_float(g0), gv1 = __uint_as_float(g1);
            float uv0 = __uint_as_float(u0), uv1 = __uint_as_float(u1);
            arow[2 * p + 0] = gv0 / (1.0f + expf(-gv0)) * uv0;
            arow[2 * p + 1] = gv1 / (1.0f + expf(-gv1)) * uv1;
        }
    }
}

// ---------------- kernel 5: GEMM2 + weighted scatter (out += comb * (a @ w2^T)) ----------------
__global__ void __launch_bounds__(256, 2)
gemm2_kernel(const int* __restrict__ w2, const int* __restrict__ w2s, float* __restrict__ out) {
    const int e = blockIdx.z;
    const int cnt = g_cnt[e];
    const int m0 = blockIdx.y * BM;
    if (m0 >= cnt) return;
    const int n0 = blockIdx.x * BN;

    __shared__ float As[BK][BM + PAD];
    __shared__ float Bs[BK][BN + PAD];
    __shared__ float tab[16];
    __shared__ int toks[BM];

    const int tid = threadIdx.x;
    if (tid < 16) tab[tid] = c_fp4[tid];
    if (tid < BM) {
        int m = m0 + tid;
        toks[tid] = g_tok[e * T_ + (m < cnt ? m : 0)];
    }
    __syncthreads();

    const int* we = w2 + (size_t)e * D_ * (I_ / 2);
    const int* se = w2s + (size_t)e * D_ * (I_ / 32);

    const int bn = tid >> 2;
    const int bw = (tid & 3) * 4;
    const int tm = (tid >> 4) << 2;
    const int tn = (tid & 15) << 2;

    unsigned long long acc2[4][2] = {};

    for (int k0 = 0; k0 < I_; k0 += BK) {
        #pragma unroll
        for (int r = 0; r < 2; r++) {
            int idx = tid + r * 256;
            int row = idx >> 3, c4 = idx & 7;
            float4 v = *reinterpret_cast<const float4*>(
                &g_a[((size_t)e * T_ + m0 + row) * I_ + k0 + c4 * 4]);
            As[c4 * 4 + 0][row] = v.x;
            As[c4 * 4 + 1][row] = v.y;
            As[c4 * 4 + 2][row] = v.z;
            As[c4 * 4 + 3][row] = v.w;
        }
        {
            int d = n0 + bn;
            float sc = __uint_as_float(((unsigned)se[d * (I_ / 32) + (k0 >> 5)]) << 23);
            int4 wv = *reinterpret_cast<const int4*>(&we[(size_t)d * (I_ / 2) + (k0 >> 1) + bw]);
            int kl = bw * 2;
            int w;
            w = wv.x; Bs[kl + 0][bn] = tab[w & 15] * sc; Bs[kl + 1][bn] = tab[(w >> 4) & 15] * sc;
            w = wv.y; Bs[kl + 2][bn] = tab[w & 15] * sc; Bs[kl + 3][bn] = tab[(w >> 4) & 15] * sc;
            w = wv.z; Bs[kl + 4][bn] = tab[w & 15] * sc; Bs[kl + 5][bn] = tab[(w >> 4) & 15] * sc;
            w = wv.w; Bs[kl + 6][bn] = tab[w & 15] * sc; Bs[kl + 7][bn] = tab[(w >> 4) & 15] * sc;
        }
        __syncthreads();

        #pragma unroll
        for (int kk = 0; kk < BK; kk++) {
            float4 av = *reinterpret_cast<const float4*>(&As[kk][tm]);
            ulonglong2 bv = *reinterpret_cast<const ulonglong2*>(&Bs[kk][tn]);
            unsigned long long a2[4];
            PACK_DUP(a2[0], av.x);
            PACK_DUP(a2[1], av.y);
            PACK_DUP(a2[2], av.z);
            PACK_DUP(a2[3], av.w);
            #pragma unroll
            for (int mi = 0; mi < 4; mi++) {
                FMA2(acc2[mi][0], a2[mi], bv.x);
                FMA2(acc2[mi][1], a2[mi], bv.y);
            }
        }
        __syncthreads();
    }

    #pragma unroll
    for (int mi = 0; mi < 4; mi++) {
        int m = m0 + tm + mi;
        if (m >= cnt) continue;
        int t = toks[tm + mi];
        float c = g_comb[t * E_ + e];
        #pragma unroll
        for (int p = 0; p < 2; p++) {
            unsigned v0, v1;
            UNPACK2(v0, v1, acc2[mi][p]);
            atomicAdd(&out[(size_t)t * D_ + n0 + tn + 2 * p + 0], c * __uint_as_float(v0));
            atomicAdd(&out[(size_t)t * D_ + n0 + tn + 2 * p + 1], c * __uint_as_float(v1));
        }
    }
}

// ---------------- launch ----------------
extern "C" void kernel_launch(void* const* d_in, const int* in_sizes, int n_in,
                              void* d_out, int out_size) {
    const float* hs   = (const float*)d_in[0];
    const float* tw   = (const float*)d_in[1];
    const int*   tids = (const int*)d_in[2];
    const int*   w13  = (const int*)d_in[3];
    const int*   w13s = (const int*)d_in[4];
    const int*   w2   = (const int*)d_in[5];
    const int*   w2s  = (const int*)d_in[6];
    float* out = (float*)d_out;

    zero_kernel<<<(T_ * D_ + 255) / 256, 256>>>(out);
    quant_kernel<<<(T_ * D_ / 32 + 7) / 8, 256>>>(hs);
    route_build<<<(T_ * K_ + 255) / 256, 256>>>(tw, tids);
    route_compact_par<<<E_, T_>>>();

    dim3 g1(I_ / BN, T_ / BM, E_);   // 12 x 8 x 16
    gemm1_kernel<<<g1, 256>>>(w13, w13s);

    dim3 g2(D_ / BN, T_ / BM, E_);   // 32 x 8 x 16
    gemm2_kernel<<<g2, 256>>>(w2, w2s, out);
}

// round 5
// speedup vs baseline: 3.8621x; 3.5676x over previous
#include <cuda_runtime.h>
#include <cuda_bf16.h>
#include <cuda_fp8.h>
#include <math.h>
#include <stdint.h>

#define T_ 512
#define D_ 2048
#define I_ 768
#define E_ 16
#define K_ 8

// ---------------- helpers ----------------
__device__ __forceinline__ uint32_t smem_u32(const void* p) {
    uint32_t a;
    asm("{ .reg .u64 t; cvta.to.shared.u64 t, %1; cvt.u32.u64 %0, t; }" : "=r"(a) : "l"(p));
    return a;
}
__device__ __forceinline__ void ldm_x4(uint32_t* r, uint32_t addr) {
    asm volatile("ldmatrix.sync.aligned.m8n8.x4.shared.b16 {%0,%1,%2,%3}, [%4];"
        : "=r"(r[0]), "=r"(r[1]), "=r"(r[2]), "=r"(r[3]) : "r"(addr));
}
__device__ __forceinline__ void mma_bf16(float* c, const uint32_t* a, const uint32_t* b) {
    asm volatile("mma.sync.aligned.m16n8k16.row.col.f32.bf16.bf16.f32 "
        "{%0,%1,%2,%3}, {%4,%5,%6,%7}, {%8,%9}, {%0,%1,%2,%3};"
        : "+f"(c[0]), "+f"(c[1]), "+f"(c[2]), "+f"(c[3])
        : "r"(a[0]), "r"(a[1]), "r"(a[2]), "r"(a[3]), "r"(b[0]), "r"(b[1]));
}

// ---------------- scratch ----------------
__device__ __nv_bfloat16 g_xb[T_ * D_];          // quant-dequantized activations (exact bf16)
__device__ __nv_bfloat16 g_ahi[E_ * T_ * I_];    // activation hi
__device__ __nv_bfloat16 g_alo[E_ * T_ * I_];    // activation lo (residual)
__device__ int   g_tok[E_ * T_];
__device__ int   g_cnt[E_];
__device__ float g_comb[T_ * E_];
__device__ int   g_flag[T_ * E_];

__constant__ float c_fp4[16] = {0.0f, 0.5f, 1.0f, 1.5f, 2.0f, 3.0f, 4.0f, 6.0f,
                                -0.0f, -0.5f, -1.0f, -1.5f, -2.0f, -3.0f, -4.0f, -6.0f};

// ---------------- small kernels ----------------
__global__ void zero_kernel(float* __restrict__ out) {
    int i = blockIdx.x * blockDim.x + threadIdx.x;
    if (i < T_ * D_) out[i] = 0.0f;
    if (i < T_ * E_) { g_comb[i] = 0.0f; g_flag[i] = 0; }
    if (i < E_) g_cnt[i] = 0;
}

__global__ void quant_kernel(const float* __restrict__ x) {
    int g = blockIdx.x * (blockDim.x >> 5) + (threadIdx.x >> 5);
    int lane = threadIdx.x & 31;
    if (g >= (T_ * D_) / 32) return;
    float v = x[g * 32 + lane];
    float av = fabsf(v);
    #pragma unroll
    for (int o = 16; o; o >>= 1) av = fmaxf(av, __shfl_xor_sync(0xffffffffu, av, o));
    av = fmaxf(av, 1e-4f);
    float scale = av / 448.0f;
    unsigned bits = __float_as_uint(scale);
    unsigned exp = ((bits >> 23) & 255u) + ((bits & 0x7fffffu) ? 1u : 0u);
    exp = min(max(exp, 1u), 254u);
    float rscale = __uint_as_float(exp << 23);
    float inv = 1.0f / rscale;
    __nv_fp8_storage_t q = __nv_cvt_float_to_fp8(v * inv, __NV_SATFINITE, __NV_E4M3);
    float qf = __half2float(__half(__nv_cvt_fp8_to_halfraw(q, __NV_E4M3)));
    g_xb[g * 32 + lane] = __float2bfloat16(qf * rscale);  // exact
}

__global__ void route_build(const float* __restrict__ tw, const int* __restrict__ tid) {
    int i = blockIdx.x * blockDim.x + threadIdx.x;
    if (i >= T_ * K_) return;
    int t = i / K_;
    int e = tid[i];
    atomicAdd(&g_comb[t * E_ + e], tw[i]);
    g_flag[t * E_ + e] = 1;
}

__global__ void route_compact_par() {
    __shared__ int s[T_];
    const int e = blockIdx.x;
    const int t = threadIdx.x;
    int f = g_flag[t * E_ + e];
    s[t] = f;
    __syncthreads();
    #pragma unroll
    for (int off = 1; off < T_; off <<= 1) {
        int v = (t >= off) ? s[t - off] : 0;
        __syncthreads();
        s[t] += v;
        __syncthreads();
    }
    if (f) g_tok[e * T_ + s[t] - 1] = t;
    if (t == T_ - 1) g_cnt[e] = s[t];
}

// fp4 byte (2 nibbles in low byte of int) -> packed bf16x2, scaled
__device__ __forceinline__ uint32_t dq2(int w, float s, const float* tab) {
    float lo = tab[w & 15] * s;
    float hi = tab[(w >> 4) & 15] * s;
    __nv_bfloat162 h = __floats2bfloat162_rn(lo, hi);
    return *reinterpret_cast<uint32_t*>(&h);
}

#define RS 144  // smem row stride bytes (64 bf16 + 16B pad): conflict-free ldmatrix

// ================= GEMM1: h = x @ w13^T, a = silu(g)*u  (mma.sync bf16) =================
__global__ void __launch_bounds__(256)
gemm1_kernel(const int* __restrict__ w13, const int* __restrict__ w13s) {
    const int e = blockIdx.z;
    const int cnt = g_cnt[e];
    const int m0 = blockIdx.y * 128;
    if (m0 >= cnt) return;
    const int n0 = blockIdx.x * 64;

    __shared__ __align__(16) unsigned char smA[128 * RS];
    __shared__ __align__(16) unsigned char smG[64 * RS];
    __shared__ __align__(16) unsigned char smU[64 * RS];
    __shared__ float tab[16];
    __shared__ int toks[128];

    const int tid = threadIdx.x, wid = tid >> 5, lid = tid & 31;
    if (tid < 16) tab[tid] = c_fp4[tid];
    if (tid < 128) toks[tid] = g_tok[e * T_ + min(m0 + tid, cnt - 1)];
    __syncthreads();

    const int* we = w13 + (size_t)e * (2 * I_) * (D_ / 2);
    const int* se = w13s + (size_t)e * (2 * I_) * (D_ / 32);
    const uint32_t aB = smem_u32(smA), gB = smem_u32(smG), uB = smem_u32(smU);
    const int wm = wid & 3, wn = wid >> 2;

    float cg[2][4][4] = {};
    float cu[2][4][4] = {};

    for (int ch = 0; ch < D_ / 64; ch++) {
        const int k0 = ch * 64;
        // A tile: 128 gathered token rows x 64 bf16
        #pragma unroll
        for (int r = 0; r < 4; r++) {
            int j = tid + r * 256;
            int row = j >> 3, seg = j & 7;
            uint4 v = *(const uint4*)&g_xb[(size_t)toks[row] * D_ + k0 + seg * 8];
            *(uint4*)(smA + row * RS + seg * 16) = v;
        }
        // B tiles: gate(64 rows) + up(64 rows), fp4 dequant
        #pragma unroll
        for (int r = 0; r < 4; r++) {
            int j = tid + r * 256;
            int half = j >> 9, jj = j & 511;
            int row = jj >> 3, seg = jj & 7;
            int f = n0 + row + half * I_;
            float s = __uint_as_float((unsigned)se[(size_t)f * (D_ / 32) + (k0 >> 5) + (seg >> 2)] << 23);
            int4 w = *(const int4*)&we[(size_t)f * (D_ / 2) + (k0 >> 1) + seg * 4];
            uint4 o;
            o.x = dq2(w.x, s, tab); o.y = dq2(w.y, s, tab);
            o.z = dq2(w.z, s, tab); o.w = dq2(w.w, s, tab);
            *(uint4*)((half ? smU : smG) + row * RS + seg * 16) = o;
        }
        __syncthreads();

        #pragma unroll
        for (int kk = 0; kk < 4; kk++) {
            uint32_t af[2][4];
            #pragma unroll
            for (int mf = 0; mf < 2; mf++)
                ldm_x4(af[mf], aB + (wm * 32 + mf * 16 + (lid & 15)) * RS + kk * 32 + (lid >> 4) * 16);
            const int nrow_off = ((lid >> 4) << 3) + (lid & 7);
            const int bcol = kk * 32 + ((lid >> 3) & 1) * 16;
            uint32_t bg[2][4], bu[2][4];
            #pragma unroll
            for (int ng = 0; ng < 2; ng++) {
                int nr = wn * 32 + ng * 16 + nrow_off;
                ldm_x4(bg[ng], gB + nr * RS + bcol);
                ldm_x4(bu[ng], uB + nr * RS + bcol);
            }
            #pragma unroll
            for (int mf = 0; mf < 2; mf++)
                #pragma unroll
                for (int ng = 0; ng < 2; ng++)
                    #pragma unroll
                    for (int sub = 0; sub < 2; sub++) {
                        mma_bf16(cg[mf][ng * 2 + sub], af[mf], &bg[ng][sub * 2]);
                        mma_bf16(cu[mf][ng * 2 + sub], af[mf], &bu[ng][sub * 2]);
                    }
        }
        __syncthreads();
    }

    // epilogue: a = silu(g)*u, hi/lo bf16 split
    #pragma unroll
    for (int mf = 0; mf < 2; mf++) {
        const int rbase = wm * 32 + mf * 16 + (lid >> 2);
        #pragma unroll
        for (int half = 0; half < 2; half++) {
            int m = m0 + rbase + half * 8;
            if (m < cnt) {
                size_t rowp = ((size_t)e * T_ + m) * I_ + n0;
                #pragma unroll
                for (int nf = 0; nf < 4; nf++) {
                    float g0 = cg[mf][nf][half * 2 + 0], g1 = cg[mf][nf][half * 2 + 1];
                    float u0 = cu[mf][nf][half * 2 + 0], u1 = cu[mf][nf][half * 2 + 1];
                    float a0 = g0 * u0 / (1.0f + __expf(-g0));
                    float a1 = g1 * u1 / (1.0f + __expf(-g1));
                    __nv_bfloat16 b0 = __float2bfloat16(a0), b1 = __float2bfloat16(a1);
                    float r0 = a0 - __bfloat162float(b0);
                    float r1 = a1 - __bfloat162float(b1);
                    int col = wn * 32 + nf * 8 + (lid & 3) * 2;
                    *(uint32_t*)&g_ahi[rowp + col] =
                        (uint32_t)__bfloat16_as_ushort(b0) | ((uint32_t)__bfloat16_as_ushort(b1) << 16);
                    __nv_bfloat162 l2 = __floats2bfloat162_rn(r0, r1);
                    *(uint32_t*)&g_alo[rowp + col] = *(uint32_t*)&l2;
                }
            }
        }
    }
}

// ================= GEMM2: out += comb * ((a_hi + a_lo) @ w2^T) =================
__global__ void __launch_bounds__(256)
gemm2_kernel(const int* __restrict__ w2, const int* __restrict__ w2s, float* __restrict__ out) {
    const int e = blockIdx.z;
    const int cnt = g_cnt[e];
    const int m0 = blockIdx.y * 128;
    if (m0 >= cnt) return;
    const int n0 = blockIdx.x * 64;

    __shared__ __align__(16) unsigned char smH[128 * RS];
    __shared__ __align__(16) unsigned char smL[128 * RS];
    __shared__ __align__(16) unsigned char smB[64 * RS];
    __shared__ float tab[16];
    __shared__ int toks[128];

    const int tid = threadIdx.x, wid = tid >> 5, lid = tid & 31;
    if (tid < 16) tab[tid] = c_fp4[tid];
    if (tid < 128) toks[tid] = g_tok[e * T_ + min(m0 + tid, cnt - 1)];
    __syncthreads();

    const int* we = w2 + (size_t)e * D_ * (I_ / 2);
    const int* se = w2s + (size_t)e * D_ * (I_ / 32);
    const uint32_t hB = smem_u32(smH), lB = smem_u32(smL), bB = smem_u32(smB);
    const int wm = wid & 3, wn = wid >> 2;

    float acc[2][4][4] = {};

    for (int ch = 0; ch < I_ / 64; ch++) {
        const int k0 = ch * 64;
        // A hi/lo tiles: 128 rows x 64 bf16 each
        #pragma unroll
        for (int r = 0; r < 8; r++) {
            int j = tid + r * 256;
            int half = j >> 10, jj = j & 1023;
            int row = jj >> 3, seg = jj & 7;
            const __nv_bfloat16* src = half ? g_alo : g_ahi;
            uint4 v = *(const uint4*)&src[((size_t)e * T_ + m0 + row) * I_ + k0 + seg * 8];
            *(uint4*)((half ? smL : smH) + row * RS + seg * 16) = v;
        }
        // B tile: 64 d-rows x 64 bf16
        #pragma unroll
        for (int r = 0; r < 2; r++) {
            int j = tid + r * 256;
            int row = j >> 3, seg = j & 7;
            int f = n0 + row;
            float s = __uint_as_float((unsigned)se[(size_t)f * (I_ / 32) + (k0 >> 5) + (seg >> 2)] << 23);
            int4 w = *(const int4*)&we[(size_t)f * (I_ / 2) + (k0 >> 1) + seg * 4];
            uint4 o;
            o.x = dq2(w.x, s, tab); o.y = dq2(w.y, s, tab);
            o.z = dq2(w.z, s, tab); o.w = dq2(w.w, s, tab);
            *(uint4*)(smB + row * RS + seg * 16) = o;
        }
        __syncthreads();

        #pragma unroll
        for (int kk = 0; kk < 4; kk++) {
            uint32_t ah[2][4], al[2][4];
            #pragma unroll
            for (int mf = 0; mf < 2; mf++) {
                uint32_t off = (wm * 32 + mf * 16 + (lid & 15)) * RS + kk * 32 + (lid >> 4) * 16;
                ldm_x4(ah[mf], hB + off);
                ldm_x4(al[mf], lB + off);
            }
            const int nrow_off = ((lid >> 4) << 3) + (lid & 7);
            const int bcol = kk * 32 + ((lid >> 3) & 1) * 16;
            uint32_t bb[2][4];
            #pragma unroll
            for (int ng = 0; ng < 2; ng++)
                ldm_x4(bb[ng], bB + (wn * 32 + ng * 16 + nrow_off) * RS + bcol);
            #pragma unroll
            for (int mf = 0; mf < 2; mf++)
                #pragma unroll
                for (int ng = 0; ng < 2; ng++)
                    #pragma unroll
                    for (int sub = 0; sub < 2; sub++) {
                        mma_bf16(acc[mf][ng * 2 + sub], ah[mf], &bb[ng][sub * 2]);
                        mma_bf16(acc[mf][ng * 2 + sub], al[mf], &bb[ng][sub * 2]);
                    }
        }
        __syncthreads();
    }

    // epilogue: weighted scatter
    #pragma unroll
    for (int mf = 0; mf < 2; mf++) {
        const int rbase = wm * 32 + mf * 16 + (lid >> 2);
        #pragma unroll
        for (int half = 0; half < 2; half++) {
            int mrow = rbase + half * 8;
            int m = m0 + mrow;
            if (m < cnt) {
                int t = toks[mrow];
                float cw = g_comb[t * E_ + e];
                float* orow = out + (size_t)t * D_ + n0;
                #pragma unroll
                for (int nf = 0; nf < 4; nf++) {
                    int col = wn * 32 + nf * 8 + (lid & 3) * 2;
                    atomicAdd(&orow[col],     cw * acc[mf][nf][half * 2 + 0]);
                    atomicAdd(&orow[col + 1], cw * acc[mf][nf][half * 2 + 1]);
                }
            }
        }
    }
}

// ---------------- launch ----------------
extern "C" void kernel_launch(void* const* d_in, const int* in_sizes, int n_in,
                              void* d_out, int out_size) {
    const float* hs   = (const float*)d_in[0];
    const float* tw   = (const float*)d_in[1];
    const int*   tids = (const int*)d_in[2];
    const int*   w13  = (const int*)d_in[3];
    const int*   w13s = (const int*)d_in[4];
    const int*   w2   = (const int*)d_in[5];
    const int*   w2s  = (const int*)d_in[6];
    float* out = (float*)d_out;

    zero_kernel<<<(T_ * D_ + 255) / 256, 256>>>(out);
    quant_kernel<<<(T_ * D_ / 32 + 7) / 8, 256>>>(hs);
    route_build<<<(T_ * K_ + 255) / 256, 256>>>(tw, tids);
    route_compact_par<<<E_, T_>>>();

    dim3 g1(I_ / 64, T_ / 128, E_);   // 12 x 4 x 16
    gemm1_kernel<<<g1, 256>>>(w13, w13s);

    dim3 g2(D_ / 64, T_ / 128, E_);   // 32 x 4 x 16
    gemm2_kernel<<<g2, 256>>>(w2, w2s, out);
}

// round 6
// speedup vs baseline: 4.9050x; 1.2700x over previous
#include <cuda_runtime.h>
#include <cuda_bf16.h>
#include <cuda_fp8.h>
#include <math.h>
#include <stdint.h>

#define T_ 512
#define D_ 2048
#define I_ 768
#define E_ 16
#define K_ 8

// ---------------- helpers ----------------
__device__ __forceinline__ uint32_t smem_u32(const void* p) {
    uint32_t a;
    asm("{ .reg .u64 t; cvta.to.shared.u64 t, %1; cvt.u32.u64 %0, t; }" : "=r"(a) : "l"(p));
    return a;
}
__device__ __forceinline__ void ldm_x4(uint32_t* r, uint32_t addr) {
    asm volatile("ldmatrix.sync.aligned.m8n8.x4.shared.b16 {%0,%1,%2,%3}, [%4];"
        : "=r"(r[0]), "=r"(r[1]), "=r"(r[2]), "=r"(r[3]) : "r"(addr));
}
__device__ __forceinline__ void mma_bf16(float* c, const uint32_t* a, const uint32_t* b) {
    asm volatile("mma.sync.aligned.m16n8k16.row.col.f32.bf16.bf16.f32 "
        "{%0,%1,%2,%3}, {%4,%5,%6,%7}, {%8,%9}, {%0,%1,%2,%3};"
        : "+f"(c[0]), "+f"(c[1]), "+f"(c[2]), "+f"(c[3])
        : "r"(a[0]), "r"(a[1]), "r"(a[2]), "r"(a[3]), "r"(b[0]), "r"(b[1]));
}

// ---------------- scratch ----------------
__device__ __nv_bfloat16 g_xb[T_ * D_];          // quant-dequantized activations (exact bf16)
__device__ __nv_bfloat16 g_ahi[E_ * T_ * I_];    // activation hi
__device__ __nv_bfloat16 g_alo[E_ * T_ * I_];    // activation lo (residual)
__device__ int   g_tok[E_ * T_];
__device__ int   g_cnt[E_];
__device__ float g_comb[T_ * E_];
__device__ int   g_flag[T_ * E_];

__constant__ float c_fp4[16] = {0.0f, 0.5f, 1.0f, 1.5f, 2.0f, 3.0f, 4.0f, 6.0f,
                                -0.0f, -0.5f, -1.0f, -1.5f, -2.0f, -3.0f, -4.0f, -6.0f};

// ---------------- small kernels ----------------
__global__ void zero_kernel(float* __restrict__ out) {
    int i = blockIdx.x * blockDim.x + threadIdx.x;
    if (i < T_ * D_) out[i] = 0.0f;
    if (i < T_ * E_) { g_comb[i] = 0.0f; g_flag[i] = 0; }
    if (i < E_) g_cnt[i] = 0;
}

__global__ void quant_kernel(const float* __restrict__ x) {
    int g = blockIdx.x * (blockDim.x >> 5) + (threadIdx.x >> 5);
    int lane = threadIdx.x & 31;
    if (g >= (T_ * D_) / 32) return;
    float v = x[g * 32 + lane];
    float av = fabsf(v);
    #pragma unroll
    for (int o = 16; o; o >>= 1) av = fmaxf(av, __shfl_xor_sync(0xffffffffu, av, o));
    av = fmaxf(av, 1e-4f);
    float scale = av / 448.0f;
    unsigned bits = __float_as_uint(scale);
    unsigned exp = ((bits >> 23) & 255u) + ((bits & 0x7fffffu) ? 1u : 0u);
    exp = min(max(exp, 1u), 254u);
    float rscale = __uint_as_float(exp << 23);
    float inv = 1.0f / rscale;
    __nv_fp8_storage_t q = __nv_cvt_float_to_fp8(v * inv, __NV_SATFINITE, __NV_E4M3);
    float qf = __half2float(__half(__nv_cvt_fp8_to_halfraw(q, __NV_E4M3)));
    g_xb[g * 32 + lane] = __float2bfloat16(qf * rscale);  // exact
}

__global__ void route_build(const float* __restrict__ tw, const int* __restrict__ tid) {
    int i = blockIdx.x * blockDim.x + threadIdx.x;
    if (i >= T_ * K_) return;
    int t = i / K_;
    int e = tid[i];
    atomicAdd(&g_comb[t * E_ + e], tw[i]);
    g_flag[t * E_ + e] = 1;
}

__global__ void route_compact_par() {
    __shared__ int s[T_];
    const int e = blockIdx.x;
    const int t = threadIdx.x;
    int f = g_flag[t * E_ + e];
    s[t] = f;
    __syncthreads();
    #pragma unroll
    for (int off = 1; off < T_; off <<= 1) {
        int v = (t >= off) ? s[t - off] : 0;
        __syncthreads();
        s[t] += v;
        __syncthreads();
    }
    if (f) g_tok[e * T_ + s[t] - 1] = t;
    if (t == T_ - 1) g_cnt[e] = s[t];
}

// fp4 byte (2 nibbles in low byte of int) -> packed bf16x2, scaled
__device__ __forceinline__ uint32_t dq2(int w, float s, const float* tab) {
    float lo = tab[w & 15] * s;
    float hi = tab[(w >> 4) & 15] * s;
    __nv_bfloat162 h = __floats2bfloat162_rn(lo, hi);
    return *reinterpret_cast<uint32_t*>(&h);
}

#define RS 144  // smem row stride bytes (64 bf16 + 16B pad): conflict-free ldmatrix

// ================= GEMM1: h = x @ w13^T, a = silu(g)*u  (mma.sync bf16, reg-pipelined) =================
__global__ void __launch_bounds__(256)
gemm1_kernel(const int* __restrict__ w13, const int* __restrict__ w13s) {
    const int e = blockIdx.z;
    const int cnt = g_cnt[e];
    const int m0 = blockIdx.y * 128;
    if (m0 >= cnt) return;
    const int n0 = blockIdx.x * 64;

    __shared__ __align__(16) unsigned char smA[128 * RS];
    __shared__ __align__(16) unsigned char smG[64 * RS];
    __shared__ __align__(16) unsigned char smU[64 * RS];
    __shared__ float tab[16];
    __shared__ int toks[128];

    const int tid = threadIdx.x, wid = tid >> 5, lid = tid & 31;
    if (tid < 16) tab[tid] = c_fp4[tid];
    if (tid < 128) toks[tid] = g_tok[e * T_ + min(m0 + tid, cnt - 1)];
    __syncthreads();

    const int* we = w13 + (size_t)e * (2 * I_) * (D_ / 2);
    const int* se = w13s + (size_t)e * (2 * I_) * (D_ / 32);
    const uint32_t aB = smem_u32(smA), gB = smem_u32(smG), uB = smem_u32(smU);
    const int wm = wid & 3, wn = wid >> 2;

    // per-thread fixed load coordinates
    int arow[4], aseg[4];
    int brow[4], bseg[4], bfeat[4];
    #pragma unroll
    for (int r = 0; r < 4; r++) {
        int j = tid + r * 256;
        arow[r] = j >> 3; aseg[r] = j & 7;
        int half = j >> 9, jj = j & 511;
        brow[r] = jj >> 3; bseg[r] = jj & 7;
        bfeat[r] = n0 + brow[r] + half * I_;
    }

    float cg[2][4][4] = {};
    float cu[2][4][4] = {};

    uint4 pa[4]; int4 pw[4]; float ps[4];
    // prefetch chunk 0
    #pragma unroll
    for (int r = 0; r < 4; r++) {
        pa[r] = *(const uint4*)&g_xb[(size_t)toks[arow[r]] * D_ + aseg[r] * 8];
        ps[r] = __uint_as_float((unsigned)se[(size_t)bfeat[r] * (D_ / 32) + (bseg[r] >> 2)] << 23);
        pw[r] = *(const int4*)&we[(size_t)bfeat[r] * (D_ / 2) + bseg[r] * 4];
    }

    const int NC = D_ / 64;
    for (int ch = 0; ch < NC; ch++) {
        // store prefetched chunk into smem (dequant weights)
        #pragma unroll
        for (int r = 0; r < 4; r++) {
            *(uint4*)(smA + arow[r] * RS + aseg[r] * 16) = pa[r];
            uint4 o;
            o.x = dq2(pw[r].x, ps[r], tab); o.y = dq2(pw[r].y, ps[r], tab);
            o.z = dq2(pw[r].z, ps[r], tab); o.w = dq2(pw[r].w, ps[r], tab);
            unsigned char* dst = (bfeat[r] >= I_) ? smU : smG;
            *(uint4*)(dst + brow[r] * RS + bseg[r] * 16) = o;
        }
        __syncthreads();

        // prefetch next chunk (overlaps with MMA below)
        if (ch + 1 < NC) {
            const int k0n = (ch + 1) * 64;
            #pragma unroll
            for (int r = 0; r < 4; r++) {
                pa[r] = *(const uint4*)&g_xb[(size_t)toks[arow[r]] * D_ + k0n + aseg[r] * 8];
                ps[r] = __uint_as_float((unsigned)se[(size_t)bfeat[r] * (D_ / 32) + (k0n >> 5) + (bseg[r] >> 2)] << 23);
                pw[r] = *(const int4*)&we[(size_t)bfeat[r] * (D_ / 2) + (k0n >> 1) + bseg[r] * 4];
            }
        }

        #pragma unroll
        for (int kk = 0; kk < 4; kk++) {
            uint32_t af[2][4];
            #pragma unroll
            for (int mf = 0; mf < 2; mf++)
                ldm_x4(af[mf], aB + (wm * 32 + mf * 16 + (lid & 15)) * RS + kk * 32 + (lid >> 4) * 16);
            const int nrow_off = ((lid >> 4) << 3) + (lid & 7);
            const int bcol = kk * 32 + ((lid >> 3) & 1) * 16;
            uint32_t bg[2][4], bu[2][4];
            #pragma unroll
            for (int ng = 0; ng < 2; ng++) {
                int nr = wn * 32 + ng * 16 + nrow_off;
                ldm_x4(bg[ng], gB + nr * RS + bcol);
                ldm_x4(bu[ng], uB + nr * RS + bcol);
            }
            #pragma unroll
            for (int mf = 0; mf < 2; mf++)
                #pragma unroll
                for (int ng = 0; ng < 2; ng++)
                    #pragma unroll
                    for (int sub = 0; sub < 2; sub++) {
                        mma_bf16(cg[mf][ng * 2 + sub], af[mf], &bg[ng][sub * 2]);
                        mma_bf16(cu[mf][ng * 2 + sub], af[mf], &bu[ng][sub * 2]);
                    }
        }
        __syncthreads();
    }

    // epilogue: a = silu(g)*u, hi/lo bf16 split
    #pragma unroll
    for (int mf = 0; mf < 2; mf++) {
        const int rbase = wm * 32 + mf * 16 + (lid >> 2);
        #pragma unroll
        for (int half = 0; half < 2; half++) {
            int m = m0 + rbase + half * 8;
            if (m < cnt) {
                size_t rowp = ((size_t)e * T_ + m) * I_ + n0;
                #pragma unroll
                for (int nf = 0; nf < 4; nf++) {
                    float g0 = cg[mf][nf][half * 2 + 0], g1 = cg[mf][nf][half * 2 + 1];
                    float u0 = cu[mf][nf][half * 2 + 0], u1 = cu[mf][nf][half * 2 + 1];
                    float a0 = g0 * u0 / (1.0f + __expf(-g0));
                    float a1 = g1 * u1 / (1.0f + __expf(-g1));
                    __nv_bfloat16 b0 = __float2bfloat16(a0), b1 = __float2bfloat16(a1);
                    float r0 = a0 - __bfloat162float(b0);
                    float r1 = a1 - __bfloat162float(b1);
                    int col = wn * 32 + nf * 8 + (lid & 3) * 2;
                    *(uint32_t*)&g_ahi[rowp + col] =
                        (uint32_t)__bfloat16_as_ushort(b0) | ((uint32_t)__bfloat16_as_ushort(b1) << 16);
                    __nv_bfloat162 l2 = __floats2bfloat162_rn(r0, r1);
                    *(uint32_t*)&g_alo[rowp + col] = *(uint32_t*)&l2;
                }
            }
        }
    }
}

// ================= GEMM2: out += comb * ((a_hi + a_lo) @ w2^T) (reg-pipelined) =================
__global__ void __launch_bounds__(256)
gemm2_kernel(const int* __restrict__ w2, const int* __restrict__ w2s, float* __restrict__ out) {
    const int e = blockIdx.z;
    const int cnt = g_cnt[e];
    const int m0 = blockIdx.y * 128;
    if (m0 >= cnt) return;
    const int n0 = blockIdx.x * 64;

    __shared__ __align__(16) unsigned char smH[128 * RS];
    __shared__ __align__(16) unsigned char smL[128 * RS];
    __shared__ __align__(16) unsigned char smB[64 * RS];
    __shared__ float tab[16];
    __shared__ int toks[128];

    const int tid = threadIdx.x, wid = tid >> 5, lid = tid & 31;
    if (tid < 16) tab[tid] = c_fp4[tid];
    if (tid < 128) toks[tid] = g_tok[e * T_ + min(m0 + tid, cnt - 1)];
    __syncthreads();

    const int* we = w2 + (size_t)e * D_ * (I_ / 2);
    const int* se = w2s + (size_t)e * D_ * (I_ / 32);
    const uint32_t hB = smem_u32(smH), lB = smem_u32(smL), bB = smem_u32(smB);
    const int wm = wid & 3, wn = wid >> 2;

    // fixed per-thread coordinates
    int arow[8], aseg[8], ahalf[8];
    #pragma unroll
    for (int r = 0; r < 8; r++) {
        int j = tid + r * 256;
        ahalf[r] = j >> 10;
        int jj = j & 1023;
        arow[r] = jj >> 3; aseg[r] = jj & 7;
    }
    int brow[2], bseg[2];
    #pragma unroll
    for (int r = 0; r < 2; r++) {
        int j = tid + r * 256;
        brow[r] = j >> 3; bseg[r] = j & 7;
    }

    float acc[2][4][4] = {};

    uint4 pa[8]; int4 pw[2]; float ps[2];
    #pragma unroll
    for (int r = 0; r < 8; r++) {
        const __nv_bfloat16* src = ahalf[r] ? g_alo : g_ahi;
        pa[r] = *(const uint4*)&src[((size_t)e * T_ + m0 + arow[r]) * I_ + aseg[r] * 8];
    }
    #pragma unroll
    for (int r = 0; r < 2; r++) {
        int f = n0 + brow[r];
        ps[r] = __uint_as_float((unsigned)se[(size_t)f * (I_ / 32) + (bseg[r] >> 2)] << 23);
        pw[r] = *(const int4*)&we[(size_t)f * (I_ / 2) + bseg[r] * 4];
    }

    const int NC = I_ / 64;
    for (int ch = 0; ch < NC; ch++) {
        #pragma unroll
        for (int r = 0; r < 8; r++)
            *(uint4*)((ahalf[r] ? smL : smH) + arow[r] * RS + aseg[r] * 16) = pa[r];
        #pragma unroll
        for (int r = 0; r < 2; r++) {
            uint4 o;
            o.x = dq2(pw[r].x, ps[r], tab); o.y = dq2(pw[r].y, ps[r], tab);
            o.z = dq2(pw[r].z, ps[r], tab); o.w = dq2(pw[r].w, ps[r], tab);
            *(uint4*)(smB + brow[r] * RS + bseg[r] * 16) = o;
        }
        __syncthreads();

        if (ch + 1 < NC) {
            const int k0n = (ch + 1) * 64;
            #pragma unroll
            for (int r = 0; r < 8; r++) {
                const __nv_bfloat16* src = ahalf[r] ? g_alo : g_ahi;
                pa[r] = *(const uint4*)&src[((size_t)e * T_ + m0 + arow[r]) * I_ + k0n + aseg[r] * 8];
            }
            #pragma unroll
            for (int r = 0; r < 2; r++) {
                int f = n0 + brow[r];
                ps[r] = __uint_as_float((unsigned)se[(size_t)f * (I_ / 32) + (k0n >> 5) + (bseg[r] >> 2)] << 23);
                pw[r] = *(const int4*)&we[(size_t)f * (I_ / 2) + (k0n >> 1) + bseg[r] * 4];
            }
        }

        #pragma unroll
        for (int kk = 0; kk < 4; kk++) {
            uint32_t ah[2][4], al[2][4];
            #pragma unroll
            for (int mf = 0; mf < 2; mf++) {
                uint32_t off = (wm * 32 + mf * 16 + (lid & 15)) * RS + kk * 32 + (lid >> 4) * 16;
                ldm_x4(ah[mf], hB + off);
                ldm_x4(al[mf], lB + off);
            }
            const int nrow_off = ((lid >> 4) << 3) + (lid & 7);
            const int bcol = kk * 32 + ((lid >> 3) & 1) * 16;
            uint32_t bb[2][4];
            #pragma unroll
            for (int ng = 0; ng < 2; ng++)
                ldm_x4(bb[ng], bB + (wn * 32 + ng * 16 + nrow_off) * RS + bcol);
            #pragma unroll
            for (int mf = 0; mf < 2; mf++)
                #pragma unroll
                for (int ng = 0; ng < 2; ng++)
                    #pragma unroll
                    for (int sub = 0; sub < 2; sub++) {
                        mma_bf16(acc[mf][ng * 2 + sub], ah[mf], &bb[ng][sub * 2]);
                        mma_bf16(acc[mf][ng * 2 + sub], al[mf], &bb[ng][sub * 2]);
                    }
        }
        __syncthreads();
    }

    // epilogue: weighted scatter
    #pragma unroll
    for (int mf = 0; mf < 2; mf++) {
        const int rbase = wm * 32 + mf * 16 + (lid >> 2);
        #pragma unroll
        for (int half = 0; half < 2; half++) {
            int mrow = rbase + half * 8;
            int m = m0 + mrow;
            if (m < cnt) {
                int t = toks[mrow];
                float cw = g_comb[t * E_ + e];
                float* orow = out + (size_t)t * D_ + n0;
                #pragma unroll
                for (int nf = 0; nf < 4; nf++) {
                    int col = wn * 32 + nf * 8 + (lid & 3) * 2;
                    atomicAdd(&orow[col],     cw * acc[mf][nf][half * 2 + 0]);
                    atomicAdd(&orow[col + 1], cw * acc[mf][nf][half * 2 + 1]);
                }
            }
        }
    }
}

// ---------------- launch ----------------
extern "C" void kernel_launch(void* const* d_in, const int* in_sizes, int n_in,
                              void* d_out, int out_size) {
    const float* hs   = (const float*)d_in[0];
    const float* tw   = (const float*)d_in[1];
    const int*   tids = (const int*)d_in[2];
    const int*   w13  = (const int*)d_in[3];
    const int*   w13s = (const int*)d_in[4];
    const int*   w2   = (const int*)d_in[5];
    const int*   w2s  = (const int*)d_in[6];
    float* out = (float*)d_out;

    zero_kernel<<<(T_ * D_ + 255) / 256, 256>>>(out);
    quant_kernel<<<(T_ * D_ / 32 + 7) / 8, 256>>>(hs);
    route_build<<<(T_ * K_ + 255) / 256, 256>>>(tw, tids);
    route_compact_par<<<E_, T_>>>();

    dim3 g1(I_ / 64, T_ / 128, E_);   // 12 x 4 x 16
    gemm1_kernel<<<g1, 256>>>(w13, w13s);

    dim3 g2(D_ / 64, T_ / 128, E_);   // 32 x 4 x 16
    gemm2_kernel<<<g2, 256>>>(w2, w2s, out);
}

// round 7
// speedup vs baseline: 5.4387x; 1.1088x over previous
#include <cuda_runtime.h>
#include <cuda_bf16.h>
#include <cuda_fp16.h>
#include <cuda_fp8.h>
#include <math.h>
#include <stdint.h>

#define T_ 512
#define D_ 2048
#define I_ 768
#define E_ 16
#define K_ 8

// ---------------- helpers ----------------
__device__ __forceinline__ uint32_t smem_u32(const void* p) {
    uint32_t a;
    asm("{ .reg .u64 t; cvta.to.shared.u64 t, %1; cvt.u32.u64 %0, t; }" : "=r"(a) : "l"(p));
    return a;
}
__device__ __forceinline__ void ldm_x4(uint32_t* r, uint32_t addr) {
    asm volatile("ldmatrix.sync.aligned.m8n8.x4.shared.b16 {%0,%1,%2,%3}, [%4];"
        : "=r"(r[0]), "=r"(r[1]), "=r"(r[2]), "=r"(r[3]) : "r"(addr));
}
__device__ __forceinline__ void mma_bf16(float* c, const uint32_t* a, const uint32_t* b) {
    asm volatile("mma.sync.aligned.m16n8k16.row.col.f32.bf16.bf16.f32 "
        "{%0,%1,%2,%3}, {%4,%5,%6,%7}, {%8,%9}, {%0,%1,%2,%3};"
        : "+f"(c[0]), "+f"(c[1]), "+f"(c[2]), "+f"(c[3])
        : "r"(a[0]), "r"(a[1]), "r"(a[2]), "r"(a[3]), "r"(b[0]), "r"(b[1]));
}
__device__ __forceinline__ void mma_f16(float* c, const uint32_t* a, const uint32_t* b) {
    asm volatile("mma.sync.aligned.m16n8k16.row.col.f32.f16.f16.f32 "
        "{%0,%1,%2,%3}, {%4,%5,%6,%7}, {%8,%9}, {%0,%1,%2,%3};"
        : "+f"(c[0]), "+f"(c[1]), "+f"(c[2]), "+f"(c[3])
        : "r"(a[0]), "r"(a[1]), "r"(a[2]), "r"(a[3]), "r"(b[0]), "r"(b[1]));
}

// ---------------- scratch ----------------
__device__ __nv_bfloat16 g_xb[T_ * D_];   // quant-dequantized activations (exact bf16)
__device__ __half g_ah[E_ * T_ * I_];     // activation a/64 in fp16
__device__ int   g_tok[E_ * T_];
__device__ int   g_cnt[E_];
__device__ float g_comb[T_ * E_];
__device__ int   g_flag[T_ * E_];

__constant__ float c_fp4[16] = {0.0f, 0.5f, 1.0f, 1.5f, 2.0f, 3.0f, 4.0f, 6.0f,
                                -0.0f, -0.5f, -1.0f, -1.5f, -2.0f, -3.0f, -4.0f, -6.0f};

// ---------------- fused preamble: zero out + fp8 quant-dequant + routing ----------------
__global__ void prep_kernel(const float* __restrict__ x,
                            const float* __restrict__ tw,
                            const int* __restrict__ tids,
                            float* __restrict__ out) {
    const int i = blockIdx.x * blockDim.x + threadIdx.x;
    if (i < T_ * D_) out[i] = 0.0f;

    // fp8 group quant-dequant: warp per 32-group
    {
        int g = i >> 5, lane = i & 31;
        if (g < (T_ * D_) / 32) {
            float v = x[g * 32 + lane];
            float av = fabsf(v);
            #pragma unroll
            for (int o = 16; o; o >>= 1) av = fmaxf(av, __shfl_xor_sync(0xffffffffu, av, o));
            av = fmaxf(av, 1e-4f);
            float scale = av / 448.0f;
            unsigned bits = __float_as_uint(scale);
            unsigned exp = ((bits >> 23) & 255u) + ((bits & 0x7fffffu) ? 1u : 0u);
            exp = min(max(exp, 1u), 254u);
            float rscale = __uint_as_float(exp << 23);
            float inv = 1.0f / rscale;
            __nv_fp8_storage_t q = __nv_cvt_float_to_fp8(v * inv, __NV_SATFINITE, __NV_E4M3);
            float qf = __half2float(__half(__nv_cvt_fp8_to_halfraw(q, __NV_E4M3)));
            g_xb[g * 32 + lane] = __float2bfloat16(qf * rscale);
        }
    }

    // routing: one thread per token, fully overwrites its comb/flag rows (no atomics)
    if (i < T_) {
        int ids[K_]; float w[K_];
        #pragma unroll
        for (int k = 0; k < K_; k++) { ids[k] = tids[i * K_ + k]; w[k] = tw[i * K_ + k]; }
        #pragma unroll
        for (int e = 0; e < E_; e++) {
            float s = 0.0f; int f = 0;
            #pragma unroll
            for (int k = 0; k < K_; k++)
                if (ids[k] == e) { s += w[k]; f = 1; }
            g_comb[i * E_ + e] = s;
            g_flag[i * E_ + e] = f;
        }
    }
}

__global__ void route_compact_par() {
    __shared__ int s[T_];
    const int e = blockIdx.x;
    const int t = threadIdx.x;
    int f = g_flag[t * E_ + e];
    s[t] = f;
    __syncthreads();
    #pragma unroll
    for (int off = 1; off < T_; off <<= 1) {
        int v = (t >= off) ? s[t - off] : 0;
        __syncthreads();
        s[t] += v;
        __syncthreads();
    }
    if (f) g_tok[e * T_ + s[t] - 1] = t;
    if (t == T_ - 1) g_cnt[e] = s[t];
}

// fp4 byte (2 nibbles) -> packed bf16x2, scaled
__device__ __forceinline__ uint32_t dq2(int w, float s, const float* tab) {
    float lo = tab[w & 15] * s;
    float hi = tab[(w >> 4) & 15] * s;
    __nv_bfloat162 h = __floats2bfloat162_rn(lo, hi);
    return *reinterpret_cast<uint32_t*>(&h);
}
// fp4 byte -> packed f16x2, scaled
__device__ __forceinline__ uint32_t dq2h(int w, float s, const float* tab) {
    float lo = tab[w & 15] * s;
    float hi = tab[(w >> 4) & 15] * s;
    __half2 h = __floats2half2_rn(lo, hi);
    return *reinterpret_cast<uint32_t*>(&h);
}

#define RS 144  // smem row stride bytes (64 elems x 2B + 16B pad): conflict-free ldmatrix

// ================= GEMM1: h = x @ w13^T, a = silu(g)*u  (bf16 mma, reg-pipelined) =================
__global__ void __launch_bounds__(256)
gemm1_kernel(const int* __restrict__ w13, const int* __restrict__ w13s) {
    const int e = blockIdx.z;
    const int cnt = g_cnt[e];
    const int m0 = blockIdx.y * 128;
    if (m0 >= cnt) return;
    const int n0 = blockIdx.x * 64;

    __shared__ __align__(16) unsigned char smA[128 * RS];
    __shared__ __align__(16) unsigned char smG[64 * RS];
    __shared__ __align__(16) unsigned char smU[64 * RS];
    __shared__ float tab[16];
    __shared__ int toks[128];

    const int tid = threadIdx.x, wid = tid >> 5, lid = tid & 31;
    if (tid < 16) tab[tid] = c_fp4[tid];
    if (tid < 128) toks[tid] = g_tok[e * T_ + min(m0 + tid, cnt - 1)];
    __syncthreads();

    const int* we = w13 + (size_t)e * (2 * I_) * (D_ / 2);
    const int* se = w13s + (size_t)e * (2 * I_) * (D_ / 32);
    const uint32_t aB = smem_u32(smA), gB = smem_u32(smG), uB = smem_u32(smU);
    const int wm = wid & 3, wn = wid >> 2;

    int arow[4], aseg[4];
    int brow[4], bseg[4], bfeat[4];
    #pragma unroll
    for (int r = 0; r < 4; r++) {
        int j = tid + r * 256;
        arow[r] = j >> 3; aseg[r] = j & 7;
        int half = j >> 9, jj = j & 511;
        brow[r] = jj >> 3; bseg[r] = jj & 7;
        bfeat[r] = n0 + brow[r] + half * I_;
    }

    float cg[2][4][4] = {};
    float cu[2][4][4] = {};

    uint4 pa[4]; int4 pw[4]; float ps[4];
    #pragma unroll
    for (int r = 0; r < 4; r++) {
        pa[r] = *(const uint4*)&g_xb[(size_t)toks[arow[r]] * D_ + aseg[r] * 8];
        ps[r] = __uint_as_float((unsigned)se[(size_t)bfeat[r] * (D_ / 32) + (bseg[r] >> 2)] << 23);
        pw[r] = *(const int4*)&we[(size_t)bfeat[r] * (D_ / 2) + bseg[r] * 4];
    }

    const int NC = D_ / 64;
    for (int ch = 0; ch < NC; ch++) {
        #pragma unroll
        for (int r = 0; r < 4; r++) {
            *(uint4*)(smA + arow[r] * RS + aseg[r] * 16) = pa[r];
            uint4 o;
            o.x = dq2(pw[r].x, ps[r], tab); o.y = dq2(pw[r].y, ps[r], tab);
            o.z = dq2(pw[r].z, ps[r], tab); o.w = dq2(pw[r].w, ps[r], tab);
            unsigned char* dst = (bfeat[r] >= I_) ? smU : smG;
            *(uint4*)(dst + brow[r] * RS + bseg[r] * 16) = o;
        }
        __syncthreads();

        if (ch + 1 < NC) {
            const int k0n = (ch + 1) * 64;
            #pragma unroll
            for (int r = 0; r < 4; r++) {
                pa[r] = *(const uint4*)&g_xb[(size_t)toks[arow[r]] * D_ + k0n + aseg[r] * 8];
                ps[r] = __uint_as_float((unsigned)se[(size_t)bfeat[r] * (D_ / 32) + (k0n >> 5) + (bseg[r] >> 2)] << 23);
                pw[r] = *(const int4*)&we[(size_t)bfeat[r] * (D_ / 2) + (k0n >> 1) + bseg[r] * 4];
            }
        }

        #pragma unroll
        for (int kk = 0; kk < 4; kk++) {
            uint32_t af[2][4];
            #pragma unroll
            for (int mf = 0; mf < 2; mf++)
                ldm_x4(af[mf], aB + (wm * 32 + mf * 16 + (lid & 15)) * RS + kk * 32 + (lid >> 4) * 16);
            const int nrow_off = ((lid >> 4) << 3) + (lid & 7);
            const int bcol = kk * 32 + ((lid >> 3) & 1) * 16;
            uint32_t bg[2][4], bu[2][4];
            #pragma unroll
            for (int ng = 0; ng < 2; ng++) {
                int nr = wn * 32 + ng * 16 + nrow_off;
                ldm_x4(bg[ng], gB + nr * RS + bcol);
                ldm_x4(bu[ng], uB + nr * RS + bcol);
            }
            #pragma unroll
            for (int mf = 0; mf < 2; mf++)
                #pragma unroll
                for (int ng = 0; ng < 2; ng++)
                    #pragma unroll
                    for (int sub = 0; sub < 2; sub++) {
                        mma_bf16(cg[mf][ng * 2 + sub], af[mf], &bg[ng][sub * 2]);
                        mma_bf16(cu[mf][ng * 2 + sub], af[mf], &bu[ng][sub * 2]);
                    }
        }
        __syncthreads();
    }

    // epilogue: a = silu(g)*u, store a/64 as fp16 (exact pow2 rescale; range-safe)
    #pragma unroll
    for (int mf = 0; mf < 2; mf++) {
        const int rbase = wm * 32 + mf * 16 + (lid >> 2);
        #pragma unroll
        for (int half = 0; half < 2; half++) {
            int m = m0 + rbase + half * 8;
            if (m < cnt) {
                size_t rowp = ((size_t)e * T_ + m) * I_ + n0;
                #pragma unroll
                for (int nf = 0; nf < 4; nf++) {
                    float g0 = cg[mf][nf][half * 2 + 0], g1 = cg[mf][nf][half * 2 + 1];
                    float u0 = cu[mf][nf][half * 2 + 0], u1 = cu[mf][nf][half * 2 + 1];
                    float a0 = g0 * u0 / (1.0f + __expf(-g0)) * 0.015625f;
                    float a1 = g1 * u1 / (1.0f + __expf(-g1)) * 0.015625f;
                    int col = wn * 32 + nf * 8 + (lid & 3) * 2;
                    __half2 h2 = __floats2half2_rn(a0, a1);
                    *(uint32_t*)&g_ah[rowp + col] = *(uint32_t*)&h2;
                }
            }
        }
    }
}

// ================= GEMM2: out += (64*comb) * ((a/64) @ w2^T)  (fp16 mma, reg-pipelined) =================
__global__ void __launch_bounds__(256)
gemm2_kernel(const int* __restrict__ w2, const int* __restrict__ w2s, float* __restrict__ out) {
    const int e = blockIdx.z;
    const int cnt = g_cnt[e];
    const int m0 = blockIdx.y * 128;
    if (m0 >= cnt) return;
    const int n0 = blockIdx.x * 64;

    __shared__ __align__(16) unsigned char smH[128 * RS];
    __shared__ __align__(16) unsigned char smB[64 * RS];
    __shared__ float tab[16];
    __shared__ int toks[128];

    const int tid = threadIdx.x, wid = tid >> 5, lid = tid & 31;
    if (tid < 16) tab[tid] = c_fp4[tid];
    if (tid < 128) toks[tid] = g_tok[e * T_ + min(m0 + tid, cnt - 1)];
    __syncthreads();

    const int* we = w2 + (size_t)e * D_ * (I_ / 2);
    const int* se = w2s + (size_t)e * D_ * (I_ / 32);
    const uint32_t hB = smem_u32(smH), bB = smem_u32(smB);
    const int wm = wid & 3, wn = wid >> 2;

    int arow[4], aseg[4];
    #pragma unroll
    for (int r = 0; r < 4; r++) {
        int j = tid + r * 256;
        arow[r] = j >> 3; aseg[r] = j & 7;
    }
    int brow[2], bseg[2];
    #pragma unroll
    for (int r = 0; r < 2; r++) {
        int j = tid + r * 256;
        brow[r] = j >> 3; bseg[r] = j & 7;
    }

    float acc[2][4][4] = {};

    uint4 pa[4]; int4 pw[2]; float ps[2];
    #pragma unroll
    for (int r = 0; r < 4; r++)
        pa[r] = *(const uint4*)&g_ah[((size_t)e * T_ + m0 + arow[r]) * I_ + aseg[r] * 8];
    #pragma unroll
    for (int r = 0; r < 2; r++) {
        int f = n0 + brow[r];
        ps[r] = __uint_as_float((unsigned)se[(size_t)f * (I_ / 32) + (bseg[r] >> 2)] << 23);
        pw[r] = *(const int4*)&we[(size_t)f * (I_ / 2) + bseg[r] * 4];
    }

    const int NC = I_ / 64;
    for (int ch = 0; ch < NC; ch++) {
        #pragma unroll
        for (int r = 0; r < 4; r++)
            *(uint4*)(smH + arow[r] * RS + aseg[r] * 16) = pa[r];
        #pragma unroll
        for (int r = 0; r < 2; r++) {
            uint4 o;
            o.x = dq2h(pw[r].x, ps[r], tab); o.y = dq2h(pw[r].y, ps[r], tab);
            o.z = dq2h(pw[r].z, ps[r], tab); o.w = dq2h(pw[r].w, ps[r], tab);
            *(uint4*)(smB + brow[r] * RS + bseg[r] * 16) = o;
        }
        __syncthreads();

        if (ch + 1 < NC) {
            const int k0n = (ch + 1) * 64;
            #pragma unroll
            for (int r = 0; r < 4; r++)
                pa[r] = *(const uint4*)&g_ah[((size_t)e * T_ + m0 + arow[r]) * I_ + k0n + aseg[r] * 8];
            #pragma unroll
            for (int r = 0; r < 2; r++) {
                int f = n0 + brow[r];
                ps[r] = __uint_as_float((unsigned)se[(size_t)f * (I_ / 32) + (k0n >> 5) + (bseg[r] >> 2)] << 23);
                pw[r] = *(const int4*)&we[(size_t)f * (I_ / 2) + (k0n >> 1) + bseg[r] * 4];
            }
        }

        #pragma unroll
        for (int kk = 0; kk < 4; kk++) {
            uint32_t ah[2][4];
            #pragma unroll
            for (int mf = 0; mf < 2; mf++)
                ldm_x4(ah[mf], hB + (wm * 32 + mf * 16 + (lid & 15)) * RS + kk * 32 + (lid >> 4) * 16);
            const int nrow_off = ((lid >> 4) << 3) + (lid & 7);
            const int bcol = kk * 32 + ((lid >> 3) & 1) * 16;
            uint32_t bb[2][4];
            #pragma unroll
            for (int ng = 0; ng < 2; ng++)
                ldm_x4(bb[ng], bB + (wn * 32 + ng * 16 + nrow_off) * RS + bcol);
            #pragma unroll
            for (int mf = 0; mf < 2; mf++)
                #pragma unroll
                for (int ng = 0; ng < 2; ng++)
                    #pragma unroll
                    for (int sub = 0; sub < 2; sub++)
                        mma_f16(acc[mf][ng * 2 + sub], ah[mf], &bb[ng][sub * 2]);
        }
        __syncthreads();
    }

    // epilogue: weighted scatter (comb * 64 compensates the a/64 storage scale)
    #pragma unroll
    for (int mf = 0; mf < 2; mf++) {
        const int rbase = wm * 32 + mf * 16 + (lid >> 2);
        #pragma unroll
        for (int half = 0; half < 2; half++) {
            int mrow = rbase + half * 8;
            int m = m0 + mrow;
            if (m < cnt) {
                int t = toks[mrow];
                float cw = g_comb[t * E_ + e] * 64.0f;
                float* orow = out + (size_t)t * D_ + n0;
                #pragma unroll
                for (int nf = 0; nf < 4; nf++) {
                    int col = wn * 32 + nf * 8 + (lid & 3) * 2;
                    atomicAdd(&orow[col],     cw * acc[mf][nf][half * 2 + 0]);
                    atomicAdd(&orow[col + 1], cw * acc[mf][nf][half * 2 + 1]);
                }
            }
        }
    }
}

// ---------------- launch ----------------
extern "C" void kernel_launch(void* const* d_in, const int* in_sizes, int n_in,
                              void* d_out, int out_size) {
    const float* hs   = (const float*)d_in[0];
    const float* tw   = (const float*)d_in[1];
    const int*   tids = (const int*)d_in[2];
    const int*   w13  = (const int*)d_in[3];
    const int*   w13s = (const int*)d_in[4];
    const int*   w2   = (const int*)d_in[5];
    const int*   w2s  = (const int*)d_in[6];
    float* out = (float*)d_out;

    prep_kernel<<<(T_ * D_ + 255) / 256, 256>>>(hs, tw, tids, out);
    route_compact_par<<<E_, T_>>>();

    dim3 g1(I_ / 64, T_ / 128, E_);   // 12 x 4 x 16
    gemm1_kernel<<<g1, 256>>>(w13, w13s);

    dim3 g2(D_ / 64, T_ / 128, E_);   // 32 x 4 x 16
    gemm2_kernel<<<g2, 256>>>(w2, w2s, out);
}

// round 8
// speedup vs baseline: 5.6840x; 1.0451x over previous
#include <cuda_runtime.h>
#include <cuda_bf16.h>
#include <cuda_fp16.h>
#include <cuda_fp8.h>
#include <math.h>
#include <stdint.h>

#define T_ 512
#define D_ 2048
#define I_ 768
#define E_ 16
#define K_ 8

// ---------------- helpers ----------------
__device__ __forceinline__ uint32_t smem_u32(const void* p) {
    uint32_t a;
    asm("{ .reg .u64 t; cvta.to.shared.u64 t, %1; cvt.u32.u64 %0, t; }" : "=r"(a) : "l"(p));
    return a;
}
__device__ __forceinline__ void ldm_x4(uint32_t* r, uint32_t addr) {
    asm volatile("ldmatrix.sync.aligned.m8n8.x4.shared.b16 {%0,%1,%2,%3}, [%4];"
        : "=r"(r[0]), "=r"(r[1]), "=r"(r[2]), "=r"(r[3]) : "r"(addr));
}
__device__ __forceinline__ void mma_bf16(float* c, const uint32_t* a, const uint32_t* b) {
    asm volatile("mma.sync.aligned.m16n8k16.row.col.f32.bf16.bf16.f32 "
        "{%0,%1,%2,%3}, {%4,%5,%6,%7}, {%8,%9}, {%0,%1,%2,%3};"
        : "+f"(c[0]), "+f"(c[1]), "+f"(c[2]), "+f"(c[3])
        : "r"(a[0]), "r"(a[1]), "r"(a[2]), "r"(a[3]), "r"(b[0]), "r"(b[1]));
}
__device__ __forceinline__ void mma_f16(float* c, const uint32_t* a, const uint32_t* b) {
    asm volatile("mma.sync.aligned.m16n8k16.row.col.f32.f16.f16.f32 "
        "{%0,%1,%2,%3}, {%4,%5,%6,%7}, {%8,%9}, {%0,%1,%2,%3};"
        : "+f"(c[0]), "+f"(c[1]), "+f"(c[2]), "+f"(c[3])
        : "r"(a[0]), "r"(a[1]), "r"(a[2]), "r"(a[3]), "r"(b[0]), "r"(b[1]));
}

// ---------------- scratch ----------------
__device__ __nv_bfloat16 g_xb[T_ * D_];   // quant-dequantized activations (exact bf16)
__device__ __half g_ah[E_ * T_ * I_];     // activation a/64 in fp16
__device__ int   g_tok[E_ * T_];
__device__ int   g_cnt[E_];
__device__ float g_comb[T_ * E_];
__device__ int   g_flag[T_ * E_];

__constant__ float c_fp4[16] = {0.0f, 0.5f, 1.0f, 1.5f, 2.0f, 3.0f, 4.0f, 6.0f,
                                -0.0f, -0.5f, -1.0f, -1.5f, -2.0f, -3.0f, -4.0f, -6.0f};

// ---------------- fused preamble: zero out + fp8 quant-dequant + routing ----------------
__global__ void prep_kernel(const float* __restrict__ x,
                            const float* __restrict__ tw,
                            const int* __restrict__ tids,
                            float* __restrict__ out) {
    const int i = blockIdx.x * blockDim.x + threadIdx.x;
    if (i < T_ * D_) out[i] = 0.0f;

    {
        int g = i >> 5, lane = i & 31;
        if (g < (T_ * D_) / 32) {
            float v = x[g * 32 + lane];
            float av = fabsf(v);
            #pragma unroll
            for (int o = 16; o; o >>= 1) av = fmaxf(av, __shfl_xor_sync(0xffffffffu, av, o));
            av = fmaxf(av, 1e-4f);
            float scale = av / 448.0f;
            unsigned bits = __float_as_uint(scale);
            unsigned exp = ((bits >> 23) & 255u) + ((bits & 0x7fffffu) ? 1u : 0u);
            exp = min(max(exp, 1u), 254u);
            float rscale = __uint_as_float(exp << 23);
            float inv = 1.0f / rscale;
            __nv_fp8_storage_t q = __nv_cvt_float_to_fp8(v * inv, __NV_SATFINITE, __NV_E4M3);
            float qf = __half2float(__half(__nv_cvt_fp8_to_halfraw(q, __NV_E4M3)));
            g_xb[g * 32 + lane] = __float2bfloat16(qf * rscale);
        }
    }

    if (i < T_) {
        int ids[K_]; float w[K_];
        #pragma unroll
        for (int k = 0; k < K_; k++) { ids[k] = tids[i * K_ + k]; w[k] = tw[i * K_ + k]; }
        #pragma unroll
        for (int e = 0; e < E_; e++) {
            float s = 0.0f; int f = 0;
            #pragma unroll
            for (int k = 0; k < K_; k++)
                if (ids[k] == e) { s += w[k]; f = 1; }
            g_comb[i * E_ + e] = s;
            g_flag[i * E_ + e] = f;
        }
    }
}

__global__ void route_compact_par() {
    __shared__ int s[T_];
    const int e = blockIdx.x;
    const int t = threadIdx.x;
    int f = g_flag[t * E_ + e];
    s[t] = f;
    __syncthreads();
    #pragma unroll
    for (int off = 1; off < T_; off <<= 1) {
        int v = (t >= off) ? s[t - off] : 0;
        __syncthreads();
        s[t] += v;
        __syncthreads();
    }
    if (f) g_tok[e * T_ + s[t] - 1] = t;
    if (t == T_ - 1) g_cnt[e] = s[t];
}

// fp4 byte (2 nibbles) -> packed bf16x2 / f16x2, scaled
__device__ __forceinline__ uint32_t dq2(int w, float s, const float* tab) {
    float lo = tab[w & 15] * s;
    float hi = tab[(w >> 4) & 15] * s;
    __nv_bfloat162 h = __floats2bfloat162_rn(lo, hi);
    return *reinterpret_cast<uint32_t*>(&h);
}
__device__ __forceinline__ uint32_t dq2h(int w, float s, const float* tab) {
    float lo = tab[w & 15] * s;
    float hi = tab[(w >> 4) & 15] * s;
    __half2 h = __floats2half2_rn(lo, hi);
    return *reinterpret_cast<uint32_t*>(&h);
}

#define RS 144  // smem row stride bytes (64 elems x 2B + 16B pad): conflict-free ldmatrix

// ================= GEMM1: h = x @ w13^T, a = silu(g)*u  (bf16 mma, reg-pipelined) =================
__global__ void __launch_bounds__(256)
gemm1_kernel(const int* __restrict__ w13, const int* __restrict__ w13s) {
    const int e = blockIdx.z;
    const int cnt = g_cnt[e];
    const int m0 = blockIdx.y * 128;
    if (m0 >= cnt) return;
    const int n0 = blockIdx.x * 64;

    __shared__ __align__(16) unsigned char smA[128 * RS];
    __shared__ __align__(16) unsigned char smG[64 * RS];
    __shared__ __align__(16) unsigned char smU[64 * RS];
    __shared__ float tab[16];
    __shared__ int toks[128];

    const int tid = threadIdx.x, wid = tid >> 5, lid = tid & 31;
    if (tid < 16) tab[tid] = c_fp4[tid];
    if (tid < 128) toks[tid] = g_tok[e * T_ + min(m0 + tid, cnt - 1)];
    __syncthreads();

    const int* we = w13 + (size_t)e * (2 * I_) * (D_ / 2);
    const int* se = w13s + (size_t)e * (2 * I_) * (D_ / 32);
    const uint32_t aB = smem_u32(smA), gB = smem_u32(smG), uB = smem_u32(smU);
    const int wm = wid & 3, wn = wid >> 2;

    int arow[4], aseg[4];
    int brow[4], bseg[4], bfeat[4];
    #pragma unroll
    for (int r = 0; r < 4; r++) {
        int j = tid + r * 256;
        arow[r] = j >> 3; aseg[r] = j & 7;
        int half = j >> 9, jj = j & 511;
        brow[r] = jj >> 3; bseg[r] = jj & 7;
        bfeat[r] = n0 + brow[r] + half * I_;
    }

    float cg[2][4][4] = {};
    float cu[2][4][4] = {};

    uint4 pa[4]; int4 pw[4]; float ps[4];
    #pragma unroll
    for (int r = 0; r < 4; r++) {
        pa[r] = *(const uint4*)&g_xb[(size_t)toks[arow[r]] * D_ + aseg[r] * 8];
        ps[r] = __uint_as_float((unsigned)se[(size_t)bfeat[r] * (D_ / 32) + (bseg[r] >> 2)] << 23);
        pw[r] = *(const int4*)&we[(size_t)bfeat[r] * (D_ / 2) + bseg[r] * 4];
    }

    const int NC = D_ / 64;
    for (int ch = 0; ch < NC; ch++) {
        #pragma unroll
        for (int r = 0; r < 4; r++) {
            *(uint4*)(smA + arow[r] * RS + aseg[r] * 16) = pa[r];
            uint4 o;
            o.x = dq2(pw[r].x, ps[r], tab); o.y = dq2(pw[r].y, ps[r], tab);
            o.z = dq2(pw[r].z, ps[r], tab); o.w = dq2(pw[r].w, ps[r], tab);
            unsigned char* dst = (bfeat[r] >= I_) ? smU : smG;
            *(uint4*)(dst + brow[r] * RS + bseg[r] * 16) = o;
        }
        __syncthreads();

        if (ch + 1 < NC) {
            const int k0n = (ch + 1) * 64;
            #pragma unroll
            for (int r = 0; r < 4; r++) {
                pa[r] = *(const uint4*)&g_xb[(size_t)toks[arow[r]] * D_ + k0n + aseg[r] * 8];
                ps[r] = __uint_as_float((unsigned)se[(size_t)bfeat[r] * (D_ / 32) + (k0n >> 5) + (bseg[r] >> 2)] << 23);
                pw[r] = *(const int4*)&we[(size_t)bfeat[r] * (D_ / 2) + (k0n >> 1) + bseg[r] * 4];
            }
        }

        #pragma unroll
        for (int kk = 0; kk < 4; kk++) {
            uint32_t af[2][4];
            #pragma unroll
            for (int mf = 0; mf < 2; mf++)
                ldm_x4(af[mf], aB + (wm * 32 + mf * 16 + (lid & 15)) * RS + kk * 32 + (lid >> 4) * 16);
            const int nrow_off = ((lid >> 4) << 3) + (lid & 7);
            const int bcol = kk * 32 + ((lid >> 3) & 1) * 16;
            uint32_t bg[2][4], bu[2][4];
            #pragma unroll
            for (int ng = 0; ng < 2; ng++) {
                int nr = wn * 32 + ng * 16 + nrow_off;
                ldm_x4(bg[ng], gB + nr * RS + bcol);
                ldm_x4(bu[ng], uB + nr * RS + bcol);
            }
            #pragma unroll
            for (int mf = 0; mf < 2; mf++)
                #pragma unroll
                for (int ng = 0; ng < 2; ng++)
                    #pragma unroll
                    for (int sub = 0; sub < 2; sub++) {
                        mma_bf16(cg[mf][ng * 2 + sub], af[mf], &bg[ng][sub * 2]);
                        mma_bf16(cu[mf][ng * 2 + sub], af[mf], &bu[ng][sub * 2]);
                    }
        }
        __syncthreads();
    }

    // epilogue: a = silu(g)*u, store a/64 as fp16
    #pragma unroll
    for (int mf = 0; mf < 2; mf++) {
        const int rbase = wm * 32 + mf * 16 + (lid >> 2);
        #pragma unroll
        for (int half = 0; half < 2; half++) {
            int m = m0 + rbase + half * 8;
            if (m < cnt) {
                size_t rowp = ((size_t)e * T_ + m) * I_ + n0;
                #pragma unroll
                for (int nf = 0; nf < 4; nf++) {
                    float g0 = cg[mf][nf][half * 2 + 0], g1 = cg[mf][nf][half * 2 + 1];
                    float u0 = cu[mf][nf][half * 2 + 0], u1 = cu[mf][nf][half * 2 + 1];
                    float a0 = g0 * u0 / (1.0f + __expf(-g0)) * 0.015625f;
                    float a1 = g1 * u1 / (1.0f + __expf(-g1)) * 0.015625f;
                    int col = wn * 32 + nf * 8 + (lid & 3) * 2;
                    __half2 h2 = __floats2half2_rn(a0, a1);
                    *(uint32_t*)&g_ah[rowp + col] = *(uint32_t*)&h2;
                }
            }
        }
    }
}

// ================= GEMM2: out += (64*comb) * ((a/64) @ w2^T)  (fp16 mma, BM=128 BN=128) =================
__global__ void __launch_bounds__(256, 2)
gemm2_kernel(const int* __restrict__ w2, const int* __restrict__ w2s, float* __restrict__ out) {
    const int e = blockIdx.z;
    const int cnt = g_cnt[e];
    const int m0 = blockIdx.y * 128;
    if (m0 >= cnt) return;
    const int n0 = blockIdx.x * 128;

    __shared__ __align__(16) unsigned char smH[128 * RS];
    __shared__ __align__(16) unsigned char smB[128 * RS];
    __shared__ float tab[16];
    __shared__ int toks[128];

    const int tid = threadIdx.x, wid = tid >> 5, lid = tid & 31;
    if (tid < 16) tab[tid] = c_fp4[tid];
    if (tid < 128) toks[tid] = g_tok[e * T_ + min(m0 + tid, cnt - 1)];
    __syncthreads();

    const int* we = w2 + (size_t)e * D_ * (I_ / 2);
    const int* se = w2s + (size_t)e * D_ * (I_ / 32);
    const uint32_t hB = smem_u32(smH), bB = smem_u32(smB);
    const int wm = wid & 3, wn = wid >> 2;   // warp tile: m32 x n64

    // shared row/seg mapping (A and B both 128 rows x 8 segs)
    int row_[4], seg_[4];
    #pragma unroll
    for (int r = 0; r < 4; r++) {
        int j = tid + r * 256;
        row_[r] = j >> 3; seg_[r] = j & 7;
    }

    float acc[2][8][4] = {};

    uint4 pa[4]; int4 pw[4]; float ps[4];
    #pragma unroll
    for (int r = 0; r < 4; r++) {
        pa[r] = *(const uint4*)&g_ah[((size_t)e * T_ + m0 + row_[r]) * I_ + seg_[r] * 8];
        int f = n0 + row_[r];
        ps[r] = __uint_as_float((unsigned)se[(size_t)f * (I_ / 32) + (seg_[r] >> 2)] << 23);
        pw[r] = *(const int4*)&we[(size_t)f * (I_ / 2) + seg_[r] * 4];
    }

    const int NC = I_ / 64;
    for (int ch = 0; ch < NC; ch++) {
        #pragma unroll
        for (int r = 0; r < 4; r++) {
            *(uint4*)(smH + row_[r] * RS + seg_[r] * 16) = pa[r];
            uint4 o;
            o.x = dq2h(pw[r].x, ps[r], tab); o.y = dq2h(pw[r].y, ps[r], tab);
            o.z = dq2h(pw[r].z, ps[r], tab); o.w = dq2h(pw[r].w, ps[r], tab);
            *(uint4*)(smB + row_[r] * RS + seg_[r] * 16) = o;
        }
        __syncthreads();

        if (ch + 1 < NC) {
            const int k0n = (ch + 1) * 64;
            #pragma unroll
            for (int r = 0; r < 4; r++) {
                pa[r] = *(const uint4*)&g_ah[((size_t)e * T_ + m0 + row_[r]) * I_ + k0n + seg_[r] * 8];
                int f = n0 + row_[r];
                ps[r] = __uint_as_float((unsigned)se[(size_t)f * (I_ / 32) + (k0n >> 5) + (seg_[r] >> 2)] << 23);
                pw[r] = *(const int4*)&we[(size_t)f * (I_ / 2) + (k0n >> 1) + seg_[r] * 4];
            }
        }

        #pragma unroll
        for (int kk = 0; kk < 4; kk++) {
            uint32_t ah[2][4];
            #pragma unroll
            for (int mf = 0; mf < 2; mf++)
                ldm_x4(ah[mf], hB + (wm * 32 + mf * 16 + (lid & 15)) * RS + kk * 32 + (lid >> 4) * 16);
            const int nrow_off = ((lid >> 4) << 3) + (lid & 7);
            const int bcol = kk * 32 + ((lid >> 3) & 1) * 16;
            #pragma unroll
            for (int hn = 0; hn < 2; hn++) {      // two n-halves to limit live regs
                uint32_t bb[2][4];
                #pragma unroll
                for (int ng = 0; ng < 2; ng++) {
                    int nr = wn * 64 + (hn * 2 + ng) * 16 + nrow_off;
                    ldm_x4(bb[ng], bB + nr * RS + bcol);
                }
                #pragma unroll
                for (int mf = 0; mf < 2; mf++)
                    #pragma unroll
                    for (int ng = 0; ng < 2; ng++)
                        #pragma unroll
                        for (int sub = 0; sub < 2; sub++)
                            mma_f16(acc[mf][(hn * 2 + ng) * 2 + sub], ah[mf], &bb[ng][sub * 2]);
            }
        }
        __syncthreads();
    }

    // epilogue: weighted scatter (comb * 64 compensates a/64)
    #pragma unroll
    for (int mf = 0; mf < 2; mf++) {
        const int rbase = wm * 32 + mf * 16 + (lid >> 2);
        #pragma unroll
        for (int half = 0; half < 2; half++) {
            int mrow = rbase + half * 8;
            int m = m0 + mrow;
            if (m < cnt) {
                int t = toks[mrow];
                float cw = g_comb[t * E_ + e] * 64.0f;
                float* orow = out + (size_t)t * D_ + n0;
                #pragma unroll
                for (int nf = 0; nf < 8; nf++) {
                    int col = wn * 64 + nf * 8 + (lid & 3) * 2;
                    atomicAdd(&orow[col],     cw * acc[mf][nf][half * 2 + 0]);
                    atomicAdd(&orow[col + 1], cw * acc[mf][nf][half * 2 + 1]);
                }
            }
        }
    }
}

// ---------------- launch ----------------
extern "C" void kernel_launch(void* const* d_in, const int* in_sizes, int n_in,
                              void* d_out, int out_size) {
    const float* hs   = (const float*)d_in[0];
    const float* tw   = (const float*)d_in[1];
    const int*   tids = (const int*)d_in[2];
    const int*   w13  = (const int*)d_in[3];
    const int*   w13s = (const int*)d_in[4];
    const int*   w2   = (const int*)d_in[5];
    const int*   w2s  = (const int*)d_in[6];
    float* out = (float*)d_out;

    prep_kernel<<<(T_ * D_ + 255) / 256, 256>>>(hs, tw, tids, out);
    route_compact_par<<<E_, T_>>>();

    dim3 g1(I_ / 64, T_ / 128, E_);    // 12 x 4 x 16
    gemm1_kernel<<<g1, 256>>>(w13, w13s);

    dim3 g2(D_ / 128, T_ / 128, E_);   // 16 x 4 x 16
    gemm2_kernel<<<g2, 256>>>(w2, w2s, out);
}